// round 14
// baseline (speedup 1.0000x reference)
#include <cuda_runtime.h>
#include <cuda_bf16.h>
#include <math.h>
#include <stdint.h>

#define BSZ  64
#define LEN  256
#define DM   512
#define DFF  2048
#define NEXP 992
#define M1   (BSZ * LEN)
#define NSPLIT 8
#define ZSCALE 0.044194173824159216f   // 1/sqrt(512)

typedef __nv_bfloat16 bf16;

// ---- dense GEMM (K-tile 32) smem strides, b32 units ----
#define AST2 20
#define BST2 136
// ---- z GEMM tiling (K-tile 16) ----
#define ASTB 12
#define BSTB 136
// ---- class GEMM tiling ----
#define AFST 12
#define ABST 9
#define BCST 72
#define CF_AB 1536
#define CF_B  576
#define CF_STAGE (2 * CF_AB + 2 * CF_B)
#define CB_AB 1152
#define CB_STAGE (2 * CB_AB + 2 * CF_B)
// fused smem pool (words): dense needs 2*2560 + 2*2176 = 9472
#define POOLW 9472

// ------------------------- scratch -------------------------
static __device__ bf16  g_X2  [(size_t)M1 * DM];
static __device__ bf16  g_XK  [(size_t)M1 * DM];
static __device__ bf16  g_EA0 [(size_t)M1 * DM];
static __device__ bf16  g_EB0 [(size_t)M1 * DM];
static __device__ bf16  g_AE  [(size_t)M1 * DM];
static __device__ bf16  g_BE  [(size_t)M1 * DM];
static __device__ float g_SEL [(size_t)M1 * DM];
static __device__ float g_X1  [(size_t)M1 * DM];
static __device__ bf16  g_ZM  [(size_t)BSZ * NEXP * LEN];
static __device__ bf16  g_CA  [(size_t)BSZ * NEXP * DM];
static __device__ bf16  g_CB  [(size_t)BSZ * NEXP * DM];
static __device__ bf16  g_H   [(size_t)M1 * DFF];
static __device__ float g_IAf [BSZ * NEXP];
static __device__ float g_IBf [BSZ * NEXP];
static __device__ float g_PA  [BSZ * NSPLIT * LEN];
static __device__ float g_PB  [BSZ * NSPLIT * LEN];
static __device__ float g_IAb [BSZ * LEN];
static __device__ float g_IBb [BSZ * LEN];
static __device__ bf16  g_WH  [3670016];           // bf16 weights [K,N]
static __device__ bf16  g_QH  [(size_t)NEXP * DM]; // bf16 q_tab

// ------------------------- helpers -------------------------
__device__ __forceinline__ uint32_t f2bf2(float lo, float hi) {
    uint32_t r;
    asm("cvt.rn.bf16x2.f32 %0, %1, %2;" : "=r"(r) : "f"(hi), "f"(lo));
    return r;
}
__device__ __forceinline__ uint32_t bfrelu2(uint32_t x) {
    uint32_t r;
    asm("max.bf16x2 %0, %1, %2;" : "=r"(r) : "r"(x), "r"(0u));
    return r;
}
__device__ __forceinline__ uint32_t bfneg2(uint32_t x) { return x ^ 0x80008000u; }
__device__ __forceinline__ float bflo(uint32_t u) { return __uint_as_float(u << 16); }
__device__ __forceinline__ float bfhi(uint32_t u) { return __uint_as_float(u & 0xffff0000u); }

__device__ __forceinline__ void mma16(float* d, const uint32_t* a, const uint32_t* b) {
    asm volatile(
        "mma.sync.aligned.m16n8k16.row.col.f32.bf16.bf16.f32 "
        "{%0,%1,%2,%3}, {%4,%5,%6,%7}, {%8,%9}, {%0,%1,%2,%3};"
        : "+f"(d[0]), "+f"(d[1]), "+f"(d[2]), "+f"(d[3])
        : "r"(a[0]), "r"(a[1]), "r"(a[2]), "r"(a[3]), "r"(b[0]), "r"(b[1]));
}

struct GArg {
    const bf16* A;
    const bf16* B;     // [K,N] row-major
    const float* bias;
    const void* Dm;
    void* C;
    int mode;
};

// ------------------------- shared GEMM bodies --------------------------------
__device__ __forceinline__ void dense_body(
    uint32_t* pool, const GArg& ga, int bm, int bn, int N, int K, int tid)
{
    uint32_t* AsU0 = pool;                 // stage stride 2560
    uint32_t* BsU0 = pool + 2 * 2560;      // stage stride 2176

    int warp = tid >> 5, lane = tid & 31;
    int wr = warp >> 1, wc = warp & 1;
    int g = lane >> 2, t4 = lane & 3;

    int arow = tid >> 1, ah16 = (tid & 1) * 16, ah8 = (tid & 1) * 8;
    int bw = tid >> 5, bc = lane * 4;

    float acc[2][8][4];
    #pragma unroll
    for (int c = 0; c < 2; c++)
        #pragma unroll
        for (int nb = 0; nb < 8; nb++)
            #pragma unroll
            for (int i = 0; i < 4; i++) acc[c][nb][i] = 0.f;

    int KT = K / 32;
    uint4 ra0, ra1;
    uint2 rb[2][2];

    auto loadregs = [&](int k0) {
        const bf16* Ap = ga.A + (size_t)(bm + arow) * K + k0 + ah16;
        ra0 = *reinterpret_cast<const uint4*>(Ap);
        ra1 = *reinterpret_cast<const uint4*>(Ap + 8);
        int krA = k0 + 2 * bw;
        rb[0][0] = *reinterpret_cast<const uint2*>(ga.B + (size_t)krA * N + bn + bc);
        rb[0][1] = *reinterpret_cast<const uint2*>(ga.B + (size_t)(krA + 1) * N + bn + bc);
        int krB = k0 + 2 * (bw + 8);
        rb[1][0] = *reinterpret_cast<const uint2*>(ga.B + (size_t)krB * N + bn + bc);
        rb[1][1] = *reinterpret_cast<const uint2*>(ga.B + (size_t)(krB + 1) * N + bn + bc);
    };
    auto storeregs = [&](int s) {
        uint32_t* ap = &AsU0[s * 2560 + arow * AST2 + ah8];
        *reinterpret_cast<uint4*>(ap) = ra0;
        *reinterpret_cast<uint4*>(ap + 4) = ra1;
        uint32_t* bp0 = &BsU0[s * 2176 + bw * BST2 + bc];
        bp0[0] = __byte_perm(rb[0][0].x, rb[0][1].x, 0x5410);
        bp0[1] = __byte_perm(rb[0][0].x, rb[0][1].x, 0x7632);
        bp0[2] = __byte_perm(rb[0][0].y, rb[0][1].y, 0x5410);
        bp0[3] = __byte_perm(rb[0][0].y, rb[0][1].y, 0x7632);
        uint32_t* bp1 = &BsU0[s * 2176 + (bw + 8) * BST2 + bc];
        bp1[0] = __byte_perm(rb[1][0].x, rb[1][1].x, 0x5410);
        bp1[1] = __byte_perm(rb[1][0].x, rb[1][1].x, 0x7632);
        bp1[2] = __byte_perm(rb[1][0].y, rb[1][1].y, 0x5410);
        bp1[3] = __byte_perm(rb[1][0].y, rb[1][1].y, 0x7632);
    };
    auto compute = [&](int s, int h) {
        uint32_t a[2][4], b[8][2];
        #pragma unroll
        for (int c = 0; c < 2; c++) {
            int row = wr * 32 + c * 16 + g;
            const uint32_t* ap = &AsU0[s * 2560 + row * AST2 + h * 8];
            a[c][0] = ap[t4];
            a[c][1] = ap[8 * AST2 + t4];
            a[c][2] = ap[t4 + 4];
            a[c][3] = ap[8 * AST2 + t4 + 4];
        }
        #pragma unroll
        for (int nb = 0; nb < 8; nb++) {
            int col = wc * 64 + nb * 8 + g;
            b[nb][0] = BsU0[s * 2176 + (h * 8 + t4) * BST2 + col];
            b[nb][1] = BsU0[s * 2176 + (h * 8 + t4 + 4) * BST2 + col];
        }
        #pragma unroll
        for (int c = 0; c < 2; c++)
            #pragma unroll
            for (int nb = 0; nb < 8; nb++)
                mma16(acc[c][nb], a[c], b[nb]);
    };

    loadregs(0);
    storeregs(0);
    __syncthreads();
    for (int t = 0; t < KT; t++) {
        if (t + 1 < KT) loadregs((t + 1) * 32);
        compute(t & 1, 0);
        compute(t & 1, 1);
        if (t + 1 < KT) storeregs((t + 1) & 1);
        __syncthreads();
    }

    int mode = ga.mode;
    #pragma unroll
    for (int c = 0; c < 2; c++) {
        #pragma unroll
        for (int nb = 0; nb < 8; nb++) {
            int n = bn + wc * 64 + nb * 8 + 2 * t4;
            float2 bi = *reinterpret_cast<const float2*>(ga.bias + n);
            #pragma unroll
            for (int h = 0; h < 2; h++) {
                int m = bm + wr * 32 + c * 16 + g + h * 8;
                size_t off = (size_t)m * N + n;
                float v0 = acc[c][nb][h * 2 + 0] + bi.x;
                float v1 = acc[c][nb][h * 2 + 1] + bi.y;
                if (mode == 1) {
                    v0 = 1.f / (1.f + expf(-v0)); v1 = 1.f / (1.f + expf(-v1));
                    *reinterpret_cast<float2*>((float*)ga.C + off) = make_float2(v0, v1);
                } else if (mode == 4) {
                    float2 d2 = *reinterpret_cast<const float2*>((const float*)ga.Dm + off);
                    *reinterpret_cast<float2*>((float*)ga.C + off) = make_float2(v0 + d2.x, v1 + d2.y);
                } else {
                    if (mode == 2) {
                        v0 = fmaxf(v0, 0.f); v1 = fmaxf(v1, 0.f);
                    } else if (mode == 3) {
                        uint32_t du = *reinterpret_cast<const uint32_t*>((const bf16*)ga.Dm + off);
                        v0 = bflo(du) / (1.f + expf(-v0));
                        v1 = bfhi(du) / (1.f + expf(-v1));
                    }
                    *reinterpret_cast<uint32_t*>((bf16*)ga.C + off) = f2bf2(v0, v1);
                }
            }
        }
    }
}

__device__ __forceinline__ void zgemm_body(
    uint32_t* pool, const int* nidx, const bf16* qh, const bf16* XK,
    const int* mask, bf16* ZM, int b, int bm, int bl, int tid)
{
    uint32_t* AsU0 = pool;                 // stage stride 1536
    uint32_t* BsU0 = pool + 2 * 1536;      // stage stride 1088
    int* sidx = reinterpret_cast<int*>(pool + 2 * 1536 + 2 * 1088);

    int warp = tid >> 5, lane = tid & 31;
    int wr = warp >> 1, wc = warp & 1;
    int g = lane >> 2, t4 = lane & 3;

    if (tid < 128) {
        int n = bm + tid;
        sidx[tid] = nidx[b * NEXP + (n < NEXP ? n : NEXP - 1)];
    }
    __syncthreads();

    float acc[2][8][4];
    #pragma unroll
    for (int c = 0; c < 2; c++)
        #pragma unroll
        for (int nb = 0; nb < 8; nb++)
            #pragma unroll
            for (int i = 0; i < 4; i++) acc[c][nb][i] = 0.f;

    int arow = tid >> 1, ac8 = (tid & 1) * 8, ac2 = (tid & 1) * 4;
    uint4 ra, rbv;
    auto loadregs = [&](int k0) {
        ra  = *reinterpret_cast<const uint4*>(qh + (size_t)sidx[arow] * DM + k0 + ac8);
        rbv = *reinterpret_cast<const uint4*>(XK + (size_t)(b * LEN + bl + arow) * DM + k0 + ac8);
    };
    auto storeregs = [&](int s) {
        *reinterpret_cast<uint4*>(&AsU0[s * 1536 + arow * ASTB + ac2]) = ra;
        BsU0[s * 1088 + (ac2 + 0) * BSTB + arow] = rbv.x;
        BsU0[s * 1088 + (ac2 + 1) * BSTB + arow] = rbv.y;
        BsU0[s * 1088 + (ac2 + 2) * BSTB + arow] = rbv.z;
        BsU0[s * 1088 + (ac2 + 3) * BSTB + arow] = rbv.w;
    };
    auto compute = [&](int s) {
        uint32_t a[2][4], bfr[8][2];
        #pragma unroll
        for (int c = 0; c < 2; c++) {
            int row = wr * 32 + c * 16 + g;
            a[c][0] = AsU0[s * 1536 + row * ASTB + t4];
            a[c][1] = AsU0[s * 1536 + (row + 8) * ASTB + t4];
            a[c][2] = AsU0[s * 1536 + row * ASTB + t4 + 4];
            a[c][3] = AsU0[s * 1536 + (row + 8) * ASTB + t4 + 4];
        }
        #pragma unroll
        for (int nb = 0; nb < 8; nb++) {
            int col = wc * 64 + nb * 8 + g;
            bfr[nb][0] = BsU0[s * 1088 + t4 * BSTB + col];
            bfr[nb][1] = BsU0[s * 1088 + (t4 + 4) * BSTB + col];
        }
        #pragma unroll
        for (int c = 0; c < 2; c++)
            #pragma unroll
            for (int nb = 0; nb < 8; nb++)
                mma16(acc[c][nb], a[c], bfr[nb]);
    };

    int KT = DM / 16;
    loadregs(0);
    storeregs(0);
    __syncthreads();
    for (int t = 0; t < KT; t++) {
        if (t + 1 < KT) loadregs((t + 1) * 16);
        compute(t & 1);
        if (t + 1 < KT) storeregs((t + 1) & 1);
        __syncthreads();
    }

    bf16* Zb = ZM + (size_t)b * NEXP * LEN;
    const int* Mb = mask + (size_t)b * NEXP * LEN;
    #pragma unroll
    for (int c = 0; c < 2; c++) {
        #pragma unroll
        for (int nb = 0; nb < 8; nb++) {
            int l = bl + wc * 64 + nb * 8 + 2 * t4;
            #pragma unroll
            for (int h = 0; h < 2; h++) {
                int n = bm + wr * 32 + c * 16 + g + h * 8;
                if (n < NEXP) {
                    size_t off = (size_t)n * LEN + l;
                    int2 m2 = *reinterpret_cast<const int2*>(Mb + off);
                    float v0 = m2.x ? acc[c][nb][h * 2 + 0] * ZSCALE : 0.f;
                    float v1 = m2.y ? acc[c][nb][h * 2 + 1] * ZSCALE : 0.f;
                    *reinterpret_cast<uint32_t*>(Zb + off) = f2bf2(v0, v1);
                }
            }
        }
    }
}

// sums body (identical math to R12 sums_fused), pool-backed smem
__device__ __forceinline__ void sums_body(
    uint32_t* pool, const bf16* ZM,
    float* invA, float* invB, float* psA, float* psB,
    int b, int s, int tid)
{
    float* colA = reinterpret_cast<float*>(pool);            // [8][LEN]
    float* colB = reinterpret_cast<float*>(pool) + 8 * LEN;  // [8][LEN]
    int warp = tid >> 5, lane = tid & 31;
    int n0 = s * (NEXP / NSPLIT);

    float ca0[4] = {}, ca1[4] = {}, cb0[4] = {}, cb1[4] = {};

    for (int r = warp; r < NEXP / NSPLIT; r += 8) {
        int n = n0 + r;
        const uint32_t* zr = reinterpret_cast<const uint32_t*>(ZM + ((size_t)b * NEXP + n) * LEN);
        float sa = 0.f, sb = 0.f;
        #pragma unroll
        for (int c = 0; c < 4; c++) {
            uint32_t u = zr[c * 32 + lane];
            float lo = bflo(u), hi = bfhi(u);
            float fa0 = fmaxf(lo, 0.f), fa1 = fmaxf(hi, 0.f);
            float fb0 = fmaxf(-lo, 0.f), fb1 = fmaxf(-hi, 0.f);
            sa += fa0 + fa1; sb += fb0 + fb1;
            ca0[c] += fa0; ca1[c] += fa1;
            cb0[c] += fb0; cb1[c] += fb1;
        }
        #pragma unroll
        for (int o = 16; o; o >>= 1) {
            sa += __shfl_down_sync(0xffffffffu, sa, o);
            sb += __shfl_down_sync(0xffffffffu, sb, o);
        }
        if (!lane) {
            invA[b * NEXP + n] = 1.f / (sa + 1e-9f);
            invB[b * NEXP + n] = 1.f / (sb + 1e-9f);
        }
    }
    #pragma unroll
    for (int c = 0; c < 4; c++) {
        colA[warp * LEN + c * 64 + 2 * lane]     = ca0[c];
        colA[warp * LEN + c * 64 + 2 * lane + 1] = ca1[c];
        colB[warp * LEN + c * 64 + 2 * lane]     = cb0[c];
        colB[warp * LEN + c * 64 + 2 * lane + 1] = cb1[c];
    }
    __syncthreads();
    int l = tid;
    float sa = 0.f, sb = 0.f;
    #pragma unroll
    for (int w = 0; w < 8; w++) { sa += colA[w * LEN + l]; sb += colB[w * LEN + l]; }
    psA[((size_t)b * NSPLIT + s) * LEN + l] = sa;
    psB[((size_t)b * NSPLIT + s) * LEN + l] = sb;
}

// ------------------------- kernels -----------------------------------------

// single/multi dense GEMM
__global__ void __launch_bounds__(256) gemm_multi(
    GArg g0, GArg g1, GArg g2, GArg g3, int M, int N, int K)
{
    __shared__ uint32_t pool[POOLW];
    GArg ga = (blockIdx.z == 0) ? g0 : (blockIdx.z == 1) ? g1 : (blockIdx.z == 2) ? g2 : g3;
    dense_body(pool, ga, blockIdx.y * 128, blockIdx.x * 128, N, K, threadIdx.x);
}

// fused: dense {Wa,Wb,Ws} (1536 CTAs) + zgemm (1024 CTAs), modulo-5 interleave
__global__ void __launch_bounds__(256) step3z_fused(
    GArg ga, GArg gb, GArg gs,
    const int* __restrict__ nidx, const bf16* __restrict__ qh,
    const bf16* __restrict__ XK, const int* __restrict__ mask, bf16* __restrict__ ZM)
{
    __shared__ uint32_t pool[POOLW];
    int bid = blockIdx.x;
    int grp = bid / 5, r = bid - grp * 5;
    if (r < 3) {
        int idx = grp * 3 + r;             // [0, 1536)
        int p = idx >> 9;
        int rr = idx & 511;
        const GArg& g = (p == 0) ? ga : (p == 1) ? gb : gs;
        dense_body(pool, g, (rr >> 2) * 128, (rr & 3) * 128, DM, DM, threadIdx.x);
    } else {
        int idx = grp * 2 + (r - 3);       // [0, 1024)
        int bl = (idx & 1) * 128;
        int bm = ((idx >> 1) & 7) * 128;
        int b  = idx >> 4;
        zgemm_body(pool, nidx, qh, XK, mask, ZM, b, bm, bl, threadIdx.x);
    }
}

// fused: gated {Wa1,Wb1} (1024 CTAs) + sums (512 CTAs), modulo-3 interleave
__global__ void __launch_bounds__(256) step4s_fused(
    GArg g1, GArg g2,
    const bf16* __restrict__ ZM,
    float* __restrict__ invA, float* __restrict__ invB,
    float* __restrict__ psA, float* __restrict__ psB)
{
    __shared__ uint32_t pool[POOLW];
    int bid = blockIdx.x;
    int grp = bid / 3, r = bid - grp * 3;
    if (r < 2) {
        int idx = grp * 2 + r;             // [0, 1024)
        int p = idx >> 9;
        int rr = idx & 511;
        dense_body(pool, p ? g2 : g1, (rr >> 2) * 128, (rr & 3) * 128, DM, DM, threadIdx.x);
    } else {
        int idx = grp;                     // [0, 512)
        sums_body(pool, ZM, invA, invB, psA, psB, idx >> 3, idx & 7, threadIdx.x);
    }
}

// fused prep: LN1 rows + weight/q_tab conversion
struct CvtArgs {
    const float* s[9];
    bf16* d[9];
    int cum[10];
};
__global__ void __launch_bounds__(128) prep_fused(
    const float* __restrict__ X, const float* __restrict__ G,
    const float* __restrict__ B, bf16* __restrict__ O, CvtArgs a)
{
    __shared__ float sred[4];
    int bid = blockIdx.x;
    if (bid < M1) {
        int row = bid;
        int t = threadIdx.x;
        const float4 v = reinterpret_cast<const float4*>(X + (size_t)row * DM)[t];
        float s = v.x + v.y + v.z + v.w;
        #pragma unroll
        for (int o = 16; o; o >>= 1) s += __shfl_down_sync(0xffffffffu, s, o);
        if ((t & 31) == 0) sred[t >> 5] = s;
        __syncthreads();
        float mu = (sred[0] + sred[1] + sred[2] + sred[3]) * (1.0f / DM);
        __syncthreads();
        float4 d;
        d.x = v.x - mu; d.y = v.y - mu; d.z = v.z - mu; d.w = v.w - mu;
        float ss = d.x * d.x + d.y * d.y + d.z * d.z + d.w * d.w;
        #pragma unroll
        for (int o = 16; o; o >>= 1) ss += __shfl_down_sync(0xffffffffu, ss, o);
        if ((t & 31) == 0) sred[t >> 5] = ss;
        __syncthreads();
        float var = (sred[0] + sred[1] + sred[2] + sred[3]) * (1.0f / DM);
        float rstd = rsqrtf(var + 1e-5f);
        const float4 g4 = reinterpret_cast<const float4*>(G)[t];
        const float4 b4 = reinterpret_cast<const float4*>(B)[t];
        uint2 o;
        o.x = f2bf2(d.x * rstd * g4.x + b4.x, d.y * rstd * g4.y + b4.y);
        o.y = f2bf2(d.z * rstd * g4.z + b4.z, d.w * rstd * g4.w + b4.w);
        reinterpret_cast<uint2*>(O + (size_t)row * DM)[t] = o;
    } else {
        int i = (bid - M1) * 128 + threadIdx.x;
        if (i < a.cum[9]) {
            int t = 0;
            #pragma unroll
            for (int j = 1; j < 9; j++) t += (i >= a.cum[j]);
            int off = i - a.cum[t];
            float4 v = reinterpret_cast<const float4*>(a.s[t])[off];
            uint2 o;
            o.x = f2bf2(v.x, v.y);
            o.y = f2bf2(v.z, v.w);
            reinterpret_cast<uint2*>(a.d[t])[off] = o;
        }
    }
}

// plain LN (used for LN2)
__global__ void ln_kernel(const float* __restrict__ X, const float* __restrict__ G,
                          const float* __restrict__ B, bf16* __restrict__ O)
{
    __shared__ float sred[4];
    int row = blockIdx.x;
    int t = threadIdx.x;
    const float4 v = reinterpret_cast<const float4*>(X + (size_t)row * DM)[t];
    float s = v.x + v.y + v.z + v.w;
    #pragma unroll
    for (int o = 16; o; o >>= 1) s += __shfl_down_sync(0xffffffffu, s, o);
    if ((t & 31) == 0) sred[t >> 5] = s;
    __syncthreads();
    float mu = (sred[0] + sred[1] + sred[2] + sred[3]) * (1.0f / DM);
    __syncthreads();
    float4 d;
    d.x = v.x - mu; d.y = v.y - mu; d.z = v.z - mu; d.w = v.w - mu;
    float ss = d.x * d.x + d.y * d.y + d.z * d.z + d.w * d.w;
    #pragma unroll
    for (int o = 16; o; o >>= 1) ss += __shfl_down_sync(0xffffffffu, ss, o);
    if ((t & 31) == 0) sred[t >> 5] = ss;
    __syncthreads();
    float var = (sred[0] + sred[1] + sred[2] + sred[3]) * (1.0f / DM);
    float rstd = rsqrtf(var + 1e-5f);
    const float4 g4 = reinterpret_cast<const float4*>(G)[t];
    const float4 b4 = reinterpret_cast<const float4*>(B)[t];
    uint2 o;
    o.x = f2bf2(d.x * rstd * g4.x + b4.x, d.y * rstd * g4.y + b4.y);
    o.y = f2bf2(d.z * rstd * g4.z + b4.z, d.w * rstd * g4.w + b4.w);
    reinterpret_cast<uint2*>(O + (size_t)row * DM)[t] = o;
}

// ------------------------- forward class GEMM + folded bw_final ------------------------------
__global__ void __launch_bounds__(256) classfw_bf16(
    const bf16* __restrict__ ZM,
    const bf16* __restrict__ AE, const bf16* __restrict__ BE,
    const float* __restrict__ invA, const float* __restrict__ invB,
    const int* __restrict__ nidx, const float* __restrict__ btab,
    bf16* __restrict__ CA, bf16* __restrict__ CB,
    const float* __restrict__ psA, const float* __restrict__ psB,
    float* __restrict__ invAb, float* __restrict__ invBb)
{
    __shared__ uint32_t sm[2][CF_STAGE];
    int bid = blockIdx.x;
    int tid = threadIdx.x;
    if (bid >= 4096) {
        // folded bw_final: 64 blocks, 256 threads
        int b = bid - 4096, l = tid;
        float sa = 0.f, sb = 0.f;
        for (int s = 0; s < NSPLIT; s++) {
            sa += psA[((size_t)b * NSPLIT + s) * LEN + l];
            sb += psB[((size_t)b * NSPLIT + s) * LEN + l];
        }
        invAb[b * LEN + l] = 1.f / (sa + 1e-9f);
        invBb[b * LEN + l] = 1.f / (sb + 1e-9f);
        return;
    }
    int b  = bid >> 6;
    int bm = ((bid >> 3) & 7) * 128;
    int bn = (bid & 7) * 64;
    int warp = tid >> 5, lane = tid & 31;
    int wr = warp >> 1, wc = warp & 1;
    int g = lane >> 2, t4 = lane & 3;

    float acca[2][4][4] = {}, accb[2][4][4] = {};

    int anr = tid >> 1, alc8 = (tid & 1) * 8, alc2 = (tid & 1) * 4;
    int bl2 = tid >> 5, bdc = lane * 2;
    uint4 za; uint32_t rE0, rE1, rB0, rB1;

    auto loadregs = [&](int k0) {
        int n = bm + anr; if (n >= NEXP) n = NEXP - 1;
        za = *reinterpret_cast<const uint4*>(ZM + ((size_t)b * NEXP + n) * LEN + k0 + alc8);
        size_t e0 = ((size_t)b * LEN + k0 + 2 * bl2) * DM + bn + bdc;
        size_t e1 = e0 + DM;
        rE0 = *reinterpret_cast<const uint32_t*>(AE + e0);
        rE1 = *reinterpret_cast<const uint32_t*>(AE + e1);
        rB0 = *reinterpret_cast<const uint32_t*>(BE + e0);
        rB1 = *reinterpret_cast<const uint32_t*>(BE + e1);
    };
    auto storeregs = [&](int s) {
        uint32_t* Aa = &sm[s][0];
        uint32_t* Ab = &sm[s][CF_AB];
        uint32_t* Ba = &sm[s][2 * CF_AB];
        uint32_t* Bb = &sm[s][2 * CF_AB + CF_B];
        uint4 ua, ub;
        ua.x = bfrelu2(za.x); ub.x = bfrelu2(bfneg2(za.x));
        ua.y = bfrelu2(za.y); ub.y = bfrelu2(bfneg2(za.y));
        ua.z = bfrelu2(za.z); ub.z = bfrelu2(bfneg2(za.z));
        ua.w = bfrelu2(za.w); ub.w = bfrelu2(bfneg2(za.w));
        *reinterpret_cast<uint4*>(&Aa[anr * AFST + alc2]) = ua;
        *reinterpret_cast<uint4*>(&Ab[anr * AFST + alc2]) = ub;
        Ba[bl2 * BCST + bdc]     = __byte_perm(rE0, rE1, 0x5410);
        Ba[bl2 * BCST + bdc + 1] = __byte_perm(rE0, rE1, 0x7632);
        Bb[bl2 * BCST + bdc]     = __byte_perm(rB0, rB1, 0x5410);
        Bb[bl2 * BCST + bdc + 1] = __byte_perm(rB0, rB1, 0x7632);
    };
    auto compute = [&](int s) {
        const uint32_t* Aa = &sm[s][0];
        const uint32_t* Ab = &sm[s][CF_AB];
        const uint32_t* Ba = &sm[s][2 * CF_AB];
        const uint32_t* Bb = &sm[s][2 * CF_AB + CF_B];
        uint32_t afa[2][4], afb[2][4], bfa[4][2], bfb[4][2];
        #pragma unroll
        for (int c = 0; c < 2; c++) {
            int row = wr * 32 + c * 16 + g;
            afa[c][0] = Aa[row * AFST + t4];
            afa[c][1] = Aa[(row + 8) * AFST + t4];
            afa[c][2] = Aa[row * AFST + t4 + 4];
            afa[c][3] = Aa[(row + 8) * AFST + t4 + 4];
            afb[c][0] = Ab[row * AFST + t4];
            afb[c][1] = Ab[(row + 8) * AFST + t4];
            afb[c][2] = Ab[row * AFST + t4 + 4];
            afb[c][3] = Ab[(row + 8) * AFST + t4 + 4];
        }
        #pragma unroll
        for (int nb = 0; nb < 4; nb++) {
            int col = wc * 32 + nb * 8 + g;
            bfa[nb][0] = Ba[t4 * BCST + col];
            bfa[nb][1] = Ba[(t4 + 4) * BCST + col];
            bfb[nb][0] = Bb[t4 * BCST + col];
            bfb[nb][1] = Bb[(t4 + 4) * BCST + col];
        }
        #pragma unroll
        for (int c = 0; c < 2; c++)
            #pragma unroll
            for (int nb = 0; nb < 4; nb++) {
                mma16(acca[c][nb], afa[c], bfa[nb]);
                mma16(accb[c][nb], afb[c], bfb[nb]);
            }
    };

    loadregs(0);
    storeregs(0);
    __syncthreads();
    const int KT = LEN / 16;
    for (int t = 0; t < KT; t++) {
        if (t + 1 < KT) loadregs((t + 1) * 16);
        compute(t & 1);
        if (t + 1 < KT) storeregs((t + 1) & 1);
        __syncthreads();
    }

    #pragma unroll
    for (int c = 0; c < 2; c++) {
        #pragma unroll
        for (int h = 0; h < 2; h++) {
            int n = bm + wr * 32 + c * 16 + g + h * 8;
            if (n >= NEXP) continue;
            float ia = invA[b * NEXP + n];
            float ib = invB[b * NEXP + n];
            int qi = nidx[b * NEXP + n];
            #pragma unroll
            for (int nb = 0; nb < 4; nb++) {
                int d0 = bn + wc * 32 + nb * 8 + 2 * t4;
                float2 bi = *reinterpret_cast<const float2*>(btab + (size_t)qi * DM + d0);
                size_t off = ((size_t)b * NEXP + n) * DM + d0;
                *reinterpret_cast<uint32_t*>(CA + off) =
                    f2bf2(acca[c][nb][h * 2 + 0] * ia + bi.x,
                          acca[c][nb][h * 2 + 1] * ia + bi.y);
                *reinterpret_cast<uint32_t*>(CB + off) =
                    f2bf2(accb[c][nb][h * 2 + 0] * ib + bi.x,
                          accb[c][nb][h * 2 + 1] * ib + bi.y);
            }
        }
    }
}

// ------------------------- backward class GEMM (mma.sync dual) -------------------------------
__global__ void __launch_bounds__(256) classbw_bf16(
    const bf16* __restrict__ ZM,
    const bf16* __restrict__ CA, const bf16* __restrict__ CB,
    const float* __restrict__ invA, const float* __restrict__ invB,
    const float* __restrict__ SELp, const float* __restrict__ X,
    float* __restrict__ X1)
{
    __shared__ uint32_t sm[2][CB_STAGE];
    int tid = threadIdx.x;
    int b  = blockIdx.z;
    int bl = blockIdx.y * 128;
    int bn = blockIdx.x * 64;
    int warp = tid >> 5, lane = tid & 31;
    int wr = warp >> 1, wc = warp & 1;
    int g = lane >> 2, t4 = lane & 3;

    float acca[2][4][4] = {}, accb[2][4][4] = {};

    int n2 = tid >> 5, l4 = lane * 4;
    int bdc = lane * 2;
    uint2 ze, zo; uint32_t rC0, rC1, rD0, rD1;

    auto loadregs = [&](int k0) {
        size_t z0 = ((size_t)b * NEXP + k0 + 2 * n2) * LEN + bl + l4;
        ze = *reinterpret_cast<const uint2*>(ZM + z0);
        zo = *reinterpret_cast<const uint2*>(ZM + z0 + LEN);
        size_t c0 = ((size_t)b * NEXP + k0 + 2 * n2) * DM + bn + bdc;
        size_t c1 = c0 + DM;
        rC0 = *reinterpret_cast<const uint32_t*>(CA + c0);
        rC1 = *reinterpret_cast<const uint32_t*>(CA + c1);
        rD0 = *reinterpret_cast<const uint32_t*>(CB + c0);
        rD1 = *reinterpret_cast<const uint32_t*>(CB + c1);
    };
    auto storeregs = [&](int s) {
        uint32_t* Aa = &sm[s][0];
        uint32_t* Ab = &sm[s][CB_AB];
        uint32_t* Ba = &sm[s][2 * CB_AB];
        uint32_t* Bb = &sm[s][2 * CB_AB + CF_B];
        uint32_t p[4];
        p[0] = __byte_perm(ze.x, zo.x, 0x5410);
        p[1] = __byte_perm(ze.x, zo.x, 0x7632);
        p[2] = __byte_perm(ze.y, zo.y, 0x5410);
        p[3] = __byte_perm(ze.y, zo.y, 0x7632);
        #pragma unroll
        for (int i = 0; i < 4; i++) {
            Aa[(l4 + i) * ABST + n2] = bfrelu2(p[i]);
            Ab[(l4 + i) * ABST + n2] = bfrelu2(bfneg2(p[i]));
        }
        Ba[n2 * BCST + bdc]     = __byte_perm(rC0, rC1, 0x5410);
        Ba[n2 * BCST + bdc + 1] = __byte_perm(rC0, rC1, 0x7632);
        Bb[n2 * BCST + bdc]     = __byte_perm(rD0, rD1, 0x5410);
        Bb[n2 * BCST + bdc + 1] = __byte_perm(rD0, rD1, 0x7632);
    };
    auto compute = [&](int s) {
        const uint32_t* Aa = &sm[s][0];
        const uint32_t* Ab = &sm[s][CB_AB];
        const uint32_t* Ba = &sm[s][2 * CB_AB];
        const uint32_t* Bb = &sm[s][2 * CB_AB + CF_B];
        uint32_t afa[2][4], afb[2][4], bfa[4][2], bfb[4][2];
        #pragma unroll
        for (int c = 0; c < 2; c++) {
            int row = wr * 32 + c * 16 + g;
            afa[c][0] = Aa[row * ABST + t4];
            afa[c][1] = Aa[(row + 8) * ABST + t4];
            afa[c][2] = Aa[row * ABST + t4 + 4];
            afa[c][3] = Aa[(row + 8) * ABST + t4 + 4];
            afb[c][0] = Ab[row * ABST + t4];
            afb[c][1] = Ab[(row + 8) * ABST + t4];
            afb[c][2] = Ab[row * ABST + t4 + 4];
            afb[c][3] = Ab[(row + 8) * ABST + t4 + 4];
        }
        #pragma unroll
        for (int nb = 0; nb < 4; nb++) {
            int col = wc * 32 + nb * 8 + g;
            bfa[nb][0] = Ba[t4 * BCST + col];
            bfa[nb][1] = Ba[(t4 + 4) * BCST + col];
            bfb[nb][0] = Bb[t4 * BCST + col];
            bfb[nb][1] = Bb[(t4 + 4) * BCST + col];
        }
        #pragma unroll
        for (int c = 0; c < 2; c++)
            #pragma unroll
            for (int nb = 0; nb < 4; nb++) {
                mma16(acca[c][nb], afa[c], bfa[nb]);
                mma16(accb[c][nb], afb[c], bfb[nb]);
            }
    };

    loadregs(0);
    storeregs(0);
    __syncthreads();
    const int KT = NEXP / 16;
    for (int t = 0; t < KT; t++) {
        if (t + 1 < KT) loadregs((t + 1) * 16);
        compute(t & 1);
        if (t + 1 < KT) storeregs((t + 1) & 1);
        __syncthreads();
    }

    #pragma unroll
    for (int c = 0; c < 2; c++) {
        #pragma unroll
        for (int h = 0; h < 2; h++) {
            int l = bl + wr * 32 + c * 16 + g + h * 8;
            float ia = invA[b * LEN + l];
            float ib = invB[b * LEN + l];
            #pragma unroll
            for (int nb = 0; nb < 4; nb++) {
                int d0 = bn + wc * 32 + nb * 8 + 2 * t4;
                size_t off = ((size_t)b * LEN + l) * DM + d0;
                float2 s2 = *reinterpret_cast<const float2*>(SELp + off);
                float2 x2 = *reinterpret_cast<const float2*>(X + off);
                float2 o;
                o.x = x2.x + s2.x * (acca[c][nb][h * 2 + 0] * ia)
                           + (1.f - s2.x) * (accb[c][nb][h * 2 + 0] * ib);
                o.y = x2.y + s2.y * (acca[c][nb][h * 2 + 1] * ia)
                           + (1.f - s2.y) * (accb[c][nb][h * 2 + 1] * ib);
                *reinterpret_cast<float2*>(X1 + off) = o;
            }
        }
    }
}

// ------------------------- launch -------------------------
extern "C" void kernel_launch(void* const* d_in, const int* in_sizes, int n_in,
                              void* d_out, int out_size)
{
    const float* x     = (const float*)d_in[0];
    const int*   nidx  = (const int*)d_in[1];
    const int*   mask  = (const int*)d_in[2];
    const float* ln1_g = (const float*)d_in[3];
    const float* ln1_b = (const float*)d_in[4];
    const float* ln2_g = (const float*)d_in[5];
    const float* ln2_b = (const float*)d_in[6];
    const float* q_tab = (const float*)d_in[7];
    const float* b_tab = (const float*)d_in[8];
    const float* Wk  = (const float*)d_in[9];  const float* bk   = (const float*)d_in[10];
    const float* Wa  = (const float*)d_in[11]; const float* ba   = (const float*)d_in[12];
    const float* Wa1 = (const float*)d_in[13]; const float* ba1  = (const float*)d_in[14];
    const float* Wb  = (const float*)d_in[15]; const float* bb   = (const float*)d_in[16];
    const float* Wb1 = (const float*)d_in[17]; const float* bb1  = (const float*)d_in[18];
    const float* Ws  = (const float*)d_in[19]; const float* bsel = (const float*)d_in[20];
    const float* Wf1 = (const float*)d_in[21]; const float* bf1  = (const float*)d_in[22];
    const float* Wf2 = (const float*)d_in[23]; const float* bf2  = (const float*)d_in[24];
    float* out = (float*)d_out;

    bf16 *pX2, *pXK, *pEA0, *pEB0, *pAE, *pBE, *pZM, *pCA, *pCB, *pH, *pWH, *pQH;
    float *pSEL, *pX1, *pIAf, *pIBf, *pPA, *pPB, *pIAb, *pIBb;
    cudaGetSymbolAddress((void**)&pX2, g_X2);
    cudaGetSymbolAddress((void**)&pXK, g_XK);
    cudaGetSymbolAddress((void**)&pEA0, g_EA0);
    cudaGetSymbolAddress((void**)&pEB0, g_EB0);
    cudaGetSymbolAddress((void**)&pAE, g_AE);
    cudaGetSymbolAddress((void**)&pBE, g_BE);
    cudaGetSymbolAddress((void**)&pSEL, g_SEL);
    cudaGetSymbolAddress((void**)&pX1, g_X1);
    cudaGetSymbolAddress((void**)&pZM, g_ZM);
    cudaGetSymbolAddress((void**)&pCA, g_CA);
    cudaGetSymbolAddress((void**)&pCB, g_CB);
    cudaGetSymbolAddress((void**)&pH, g_H);
    cudaGetSymbolAddress((void**)&pIAf, g_IAf);
    cudaGetSymbolAddress((void**)&pIBf, g_IBf);
    cudaGetSymbolAddress((void**)&pPA, g_PA);
    cudaGetSymbolAddress((void**)&pPB, g_PB);
    cudaGetSymbolAddress((void**)&pIAb, g_IAb);
    cudaGetSymbolAddress((void**)&pIBb, g_IBb);
    cudaGetSymbolAddress((void**)&pWH, g_WH);
    cudaGetSymbolAddress((void**)&pQH, g_QH);

    bf16* WkH  = pWH;
    bf16* WaH  = pWH + 262144;
    bf16* WbH  = pWH + 524288;
    bf16* WsH  = pWH + 786432;
    bf16* Wa1H = pWH + 1048576;
    bf16* Wb1H = pWH + 1310720;
    bf16* Wf1H = pWH + 1572864;
    bf16* Wf2H = pWH + 2621440;

    // 0. fused LN1 + weight conversion
    CvtArgs ca;
    ca.s[0] = Wk;  ca.d[0] = WkH;
    ca.s[1] = Wa;  ca.d[1] = WaH;
    ca.s[2] = Wb;  ca.d[2] = WbH;
    ca.s[3] = Ws;  ca.d[3] = WsH;
    ca.s[4] = Wa1; ca.d[4] = Wa1H;
    ca.s[5] = Wb1; ca.d[5] = Wb1H;
    ca.s[6] = Wf1; ca.d[6] = Wf1H;
    ca.s[7] = Wf2; ca.d[7] = Wf2H;
    ca.s[8] = q_tab; ca.d[8] = pQH;
    int sizes4[9] = {65536, 65536, 65536, 65536, 65536, 65536, 262144, 262144, 126976};
    ca.cum[0] = 0;
    for (int i = 0; i < 9; i++) ca.cum[i + 1] = ca.cum[i] + sizes4[i];
    int cvtBlocks = (ca.cum[9] + 127) / 128;
    prep_fused<<<M1 + cvtBlocks, 128>>>(x, ln1_g, ln1_b, pX2, ca);

    // 1. Wk projection only (critical path to zgemm)
    GArg gk = {pX2, WkH, bk, nullptr, pXK, 0};
    gemm_multi<<<dim3(DM / 128, M1 / 128, 1), 256>>>(gk, gk, gk, gk, M1, DM, DM);

    // 2. fused: {Wa, Wb, Ws} projections + z GEMM
    GArg ga_ = {pX2, WaH, ba,  nullptr, pEA0, 0};
    GArg gb = {pX2, WbH, bb,   nullptr, pEB0, 0};
    GArg gs = {pX2, WsH, bsel, nullptr, pSEL, 1};
    step3z_fused<<<2560, 256>>>(ga_, gb, gs, nidx, pQH, pXK, mask, pZM);

    // 3. fused: gated {Wa1, Wb1} + sums
    GArg g1 = {pEA0, Wa1H, ba1, pEA0, pAE, 3};
    GArg g2 = {pEB0, Wb1H, bb1, pEB0, pBE, 3};
    step4s_fused<<<1536, 256>>>(g1, g2, pZM, pIAf, pIBf, pPA, pPB);

    // 4. classfw + folded bw_final
    classfw_bf16<<<4096 + 64, 256>>>(pZM, pAE, pBE, pIAf, pIBf, nidx, b_tab,
                                     pCA, pCB, pPA, pPB, pIAb, pIBb);

    // 5. classbw
    classbw_bf16<<<dim3(DM / 64, LEN / 128, BSZ), 256>>>(
        pZM, pCA, pCB, pIAb, pIBb, pSEL, x, pX1);

    // 6. LN2 + FFN
    ln_kernel<<<M1, 128>>>(pX1, ln2_g, ln2_b, pX2);
    GArg gf1 = {pX2, Wf1H, bf1, nullptr, pH, 2};
    gemm_multi<<<dim3(DFF / 128, M1 / 128, 1), 256>>>(gf1, gf1, gf1, gf1, M1, DFF, DM);
    GArg gf2 = {pH, Wf2H, bf2, pX1, out, 4};
    gemm_multi<<<dim3(DM / 128, M1 / 128, 1), 256>>>(gf2, gf2, gf2, gf2, M1, DM, DFF);
}

// round 15
// speedup vs baseline: 1.0318x; 1.0318x over previous
#include <cuda_runtime.h>
#include <cuda_bf16.h>
#include <math.h>
#include <stdint.h>

#define BSZ  64
#define LEN  256
#define DM   512
#define DFF  2048
#define NEXP 992
#define M1   (BSZ * LEN)
#define NSPLIT 8
#define ZSCALE 0.044194173824159216f   // 1/sqrt(512)

typedef __nv_bfloat16 bf16;

// ---- dense GEMM (K-tile 32) smem strides, b32 units ----
#define AST2 20
#define BST2 136
// ---- z GEMM tiling (K-tile 16) ----
#define ASTB 12
#define BSTB 136
// ---- class GEMM tiling ----
#define AFST 12
#define ABST 9
#define BCST 72
#define CF_AB 1536
#define CF_B  576
#define CF_STAGE (2 * CF_AB + 2 * CF_B)
#define CB_AB 1152
#define CB_STAGE (2 * CB_AB + 2 * CF_B)
// fused smem pool (words): dense needs 2*2560 + 2*2176 = 9472
#define POOLW 9472

// ------------------------- scratch -------------------------
static __device__ bf16  g_X2  [(size_t)M1 * DM];
static __device__ bf16  g_XK  [(size_t)M1 * DM];
static __device__ bf16  g_EA0 [(size_t)M1 * DM];
static __device__ bf16  g_EB0 [(size_t)M1 * DM];
static __device__ bf16  g_AE  [(size_t)M1 * DM];
static __device__ bf16  g_BE  [(size_t)M1 * DM];
static __device__ float g_SEL [(size_t)M1 * DM];
static __device__ float g_X1  [(size_t)M1 * DM];
static __device__ bf16  g_ZM  [(size_t)BSZ * NEXP * LEN];
static __device__ bf16  g_CA  [(size_t)BSZ * NEXP * DM];
static __device__ bf16  g_CB  [(size_t)BSZ * NEXP * DM];
static __device__ bf16  g_H   [(size_t)M1 * DFF];
static __device__ float g_IAf [BSZ * NEXP];
static __device__ float g_IBf [BSZ * NEXP];
static __device__ float g_PA  [BSZ * NSPLIT * LEN];
static __device__ float g_PB  [BSZ * NSPLIT * LEN];
static __device__ float g_IAb [BSZ * LEN];
static __device__ float g_IBb [BSZ * LEN];
static __device__ bf16  g_WH  [3670016];           // bf16 weights [K,N]
static __device__ bf16  g_QH  [(size_t)NEXP * DM]; // bf16 q_tab

// ------------------------- helpers -------------------------
__device__ __forceinline__ uint32_t f2bf2(float lo, float hi) {
    uint32_t r;
    asm("cvt.rn.bf16x2.f32 %0, %1, %2;" : "=r"(r) : "f"(hi), "f"(lo));
    return r;
}
__device__ __forceinline__ uint32_t bfrelu2(uint32_t x) {
    uint32_t r;
    asm("max.bf16x2 %0, %1, %2;" : "=r"(r) : "r"(x), "r"(0u));
    return r;
}
__device__ __forceinline__ uint32_t bfneg2(uint32_t x) { return x ^ 0x80008000u; }
__device__ __forceinline__ float bflo(uint32_t u) { return __uint_as_float(u << 16); }
__device__ __forceinline__ float bfhi(uint32_t u) { return __uint_as_float(u & 0xffff0000u); }

__device__ __forceinline__ void mma16(float* d, const uint32_t* a, const uint32_t* b) {
    asm volatile(
        "mma.sync.aligned.m16n8k16.row.col.f32.bf16.bf16.f32 "
        "{%0,%1,%2,%3}, {%4,%5,%6,%7}, {%8,%9}, {%0,%1,%2,%3};"
        : "+f"(d[0]), "+f"(d[1]), "+f"(d[2]), "+f"(d[3])
        : "r"(a[0]), "r"(a[1]), "r"(a[2]), "r"(a[3]), "r"(b[0]), "r"(b[1]));
}

struct GArg {
    const bf16* A;
    const bf16* B;     // [K,N] row-major
    const float* bias;
    const void* Dm;
    void* C;
    int mode;
};

// ------------------------- shared GEMM bodies --------------------------------
// dense 128x128, K-tile 32
__device__ __forceinline__ void dense_body(
    uint32_t* pool, const GArg& ga, int bm, int bn, int N, int K, int tid)
{
    uint32_t* AsU0 = pool;                 // stage stride 2560
    uint32_t* BsU0 = pool + 2 * 2560;      // stage stride 2176

    int warp = tid >> 5, lane = tid & 31;
    int wr = warp >> 1, wc = warp & 1;
    int g = lane >> 2, t4 = lane & 3;

    int arow = tid >> 1, ah16 = (tid & 1) * 16, ah8 = (tid & 1) * 8;
    int bw = tid >> 5, bc = lane * 4;

    float acc[2][8][4];
    #pragma unroll
    for (int c = 0; c < 2; c++)
        #pragma unroll
        for (int nb = 0; nb < 8; nb++)
            #pragma unroll
            for (int i = 0; i < 4; i++) acc[c][nb][i] = 0.f;

    int KT = K / 32;
    uint4 ra0, ra1;
    uint2 rb[2][2];

    auto loadregs = [&](int k0) {
        const bf16* Ap = ga.A + (size_t)(bm + arow) * K + k0 + ah16;
        ra0 = *reinterpret_cast<const uint4*>(Ap);
        ra1 = *reinterpret_cast<const uint4*>(Ap + 8);
        int krA = k0 + 2 * bw;
        rb[0][0] = *reinterpret_cast<const uint2*>(ga.B + (size_t)krA * N + bn + bc);
        rb[0][1] = *reinterpret_cast<const uint2*>(ga.B + (size_t)(krA + 1) * N + bn + bc);
        int krB = k0 + 2 * (bw + 8);
        rb[1][0] = *reinterpret_cast<const uint2*>(ga.B + (size_t)krB * N + bn + bc);
        rb[1][1] = *reinterpret_cast<const uint2*>(ga.B + (size_t)(krB + 1) * N + bn + bc);
    };
    auto storeregs = [&](int s) {
        uint32_t* ap = &AsU0[s * 2560 + arow * AST2 + ah8];
        *reinterpret_cast<uint4*>(ap) = ra0;
        *reinterpret_cast<uint4*>(ap + 4) = ra1;
        uint32_t* bp0 = &BsU0[s * 2176 + bw * BST2 + bc];
        bp0[0] = __byte_perm(rb[0][0].x, rb[0][1].x, 0x5410);
        bp0[1] = __byte_perm(rb[0][0].x, rb[0][1].x, 0x7632);
        bp0[2] = __byte_perm(rb[0][0].y, rb[0][1].y, 0x5410);
        bp0[3] = __byte_perm(rb[0][0].y, rb[0][1].y, 0x7632);
        uint32_t* bp1 = &BsU0[s * 2176 + (bw + 8) * BST2 + bc];
        bp1[0] = __byte_perm(rb[1][0].x, rb[1][1].x, 0x5410);
        bp1[1] = __byte_perm(rb[1][0].x, rb[1][1].x, 0x7632);
        bp1[2] = __byte_perm(rb[1][0].y, rb[1][1].y, 0x5410);
        bp1[3] = __byte_perm(rb[1][0].y, rb[1][1].y, 0x7632);
    };
    auto compute = [&](int s, int h) {
        uint32_t a[2][4], b[8][2];
        #pragma unroll
        for (int c = 0; c < 2; c++) {
            int row = wr * 32 + c * 16 + g;
            const uint32_t* ap = &AsU0[s * 2560 + row * AST2 + h * 8];
            a[c][0] = ap[t4];
            a[c][1] = ap[8 * AST2 + t4];
            a[c][2] = ap[t4 + 4];
            a[c][3] = ap[8 * AST2 + t4 + 4];
        }
        #pragma unroll
        for (int nb = 0; nb < 8; nb++) {
            int col = wc * 64 + nb * 8 + g;
            b[nb][0] = BsU0[s * 2176 + (h * 8 + t4) * BST2 + col];
            b[nb][1] = BsU0[s * 2176 + (h * 8 + t4 + 4) * BST2 + col];
        }
        #pragma unroll
        for (int c = 0; c < 2; c++)
            #pragma unroll
            for (int nb = 0; nb < 8; nb++)
                mma16(acc[c][nb], a[c], b[nb]);
    };

    loadregs(0);
    storeregs(0);
    __syncthreads();
    for (int t = 0; t < KT; t++) {
        if (t + 1 < KT) loadregs((t + 1) * 32);
        compute(t & 1, 0);
        compute(t & 1, 1);
        if (t + 1 < KT) storeregs((t + 1) & 1);
        __syncthreads();
    }

    int mode = ga.mode;
    #pragma unroll
    for (int c = 0; c < 2; c++) {
        #pragma unroll
        for (int nb = 0; nb < 8; nb++) {
            int n = bn + wc * 64 + nb * 8 + 2 * t4;
            float2 bi = *reinterpret_cast<const float2*>(ga.bias + n);
            #pragma unroll
            for (int h = 0; h < 2; h++) {
                int m = bm + wr * 32 + c * 16 + g + h * 8;
                size_t off = (size_t)m * N + n;
                float v0 = acc[c][nb][h * 2 + 0] + bi.x;
                float v1 = acc[c][nb][h * 2 + 1] + bi.y;
                if (mode == 1) {
                    v0 = 1.f / (1.f + expf(-v0)); v1 = 1.f / (1.f + expf(-v1));
                    *reinterpret_cast<float2*>((float*)ga.C + off) = make_float2(v0, v1);
                } else if (mode == 4) {
                    float2 d2 = *reinterpret_cast<const float2*>((const float*)ga.Dm + off);
                    *reinterpret_cast<float2*>((float*)ga.C + off) = make_float2(v0 + d2.x, v1 + d2.y);
                } else {
                    if (mode == 2) {
                        v0 = fmaxf(v0, 0.f); v1 = fmaxf(v1, 0.f);
                    } else if (mode == 3) {
                        uint32_t du = *reinterpret_cast<const uint32_t*>((const bf16*)ga.Dm + off);
                        v0 = bflo(du) / (1.f + expf(-v0));
                        v1 = bfhi(du) / (1.f + expf(-v1));
                    }
                    *reinterpret_cast<uint32_t*>((bf16*)ga.C + off) = f2bf2(v0, v1);
                }
            }
        }
    }
}

__device__ __forceinline__ void zgemm_body(
    uint32_t* pool, const int* nidx, const bf16* qh, const bf16* XK,
    const int* mask, bf16* ZM, int b, int bm, int bl, int tid)
{
    uint32_t* AsU0 = pool;                 // stage stride 1536
    uint32_t* BsU0 = pool + 2 * 1536;      // stage stride 1088
    int* sidx = reinterpret_cast<int*>(pool + 2 * 1536 + 2 * 1088);

    int warp = tid >> 5, lane = tid & 31;
    int wr = warp >> 1, wc = warp & 1;
    int g = lane >> 2, t4 = lane & 3;

    if (tid < 128) {
        int n = bm + tid;
        sidx[tid] = nidx[b * NEXP + (n < NEXP ? n : NEXP - 1)];
    }
    __syncthreads();

    float acc[2][8][4];
    #pragma unroll
    for (int c = 0; c < 2; c++)
        #pragma unroll
        for (int nb = 0; nb < 8; nb++)
            #pragma unroll
            for (int i = 0; i < 4; i++) acc[c][nb][i] = 0.f;

    int arow = tid >> 1, ac8 = (tid & 1) * 8, ac2 = (tid & 1) * 4;
    uint4 ra, rbv;
    auto loadregs = [&](int k0) {
        ra  = *reinterpret_cast<const uint4*>(qh + (size_t)sidx[arow] * DM + k0 + ac8);
        rbv = *reinterpret_cast<const uint4*>(XK + (size_t)(b * LEN + bl + arow) * DM + k0 + ac8);
    };
    auto storeregs = [&](int s) {
        *reinterpret_cast<uint4*>(&AsU0[s * 1536 + arow * ASTB + ac2]) = ra;
        BsU0[s * 1088 + (ac2 + 0) * BSTB + arow] = rbv.x;
        BsU0[s * 1088 + (ac2 + 1) * BSTB + arow] = rbv.y;
        BsU0[s * 1088 + (ac2 + 2) * BSTB + arow] = rbv.z;
        BsU0[s * 1088 + (ac2 + 3) * BSTB + arow] = rbv.w;
    };
    auto compute = [&](int s) {
        uint32_t a[2][4], bfr[8][2];
        #pragma unroll
        for (int c = 0; c < 2; c++) {
            int row = wr * 32 + c * 16 + g;
            a[c][0] = AsU0[s * 1536 + row * ASTB + t4];
            a[c][1] = AsU0[s * 1536 + (row + 8) * ASTB + t4];
            a[c][2] = AsU0[s * 1536 + row * ASTB + t4 + 4];
            a[c][3] = AsU0[s * 1536 + (row + 8) * ASTB + t4 + 4];
        }
        #pragma unroll
        for (int nb = 0; nb < 8; nb++) {
            int col = wc * 64 + nb * 8 + g;
            bfr[nb][0] = BsU0[s * 1088 + t4 * BSTB + col];
            bfr[nb][1] = BsU0[s * 1088 + (t4 + 4) * BSTB + col];
        }
        #pragma unroll
        for (int c = 0; c < 2; c++)
            #pragma unroll
            for (int nb = 0; nb < 8; nb++)
                mma16(acc[c][nb], a[c], bfr[nb]);
    };

    int KT = DM / 16;
    loadregs(0);
    storeregs(0);
    __syncthreads();
    for (int t = 0; t < KT; t++) {
        if (t + 1 < KT) loadregs((t + 1) * 16);
        compute(t & 1);
        if (t + 1 < KT) storeregs((t + 1) & 1);
        __syncthreads();
    }

    bf16* Zb = ZM + (size_t)b * NEXP * LEN;
    const int* Mb = mask + (size_t)b * NEXP * LEN;
    #pragma unroll
    for (int c = 0; c < 2; c++) {
        #pragma unroll
        for (int nb = 0; nb < 8; nb++) {
            int l = bl + wc * 64 + nb * 8 + 2 * t4;
            #pragma unroll
            for (int h = 0; h < 2; h++) {
                int n = bm + wr * 32 + c * 16 + g + h * 8;
                if (n < NEXP) {
                    size_t off = (size_t)n * LEN + l;
                    int2 m2 = *reinterpret_cast<const int2*>(Mb + off);
                    float v0 = m2.x ? acc[c][nb][h * 2 + 0] * ZSCALE : 0.f;
                    float v1 = m2.y ? acc[c][nb][h * 2 + 1] * ZSCALE : 0.f;
                    *reinterpret_cast<uint32_t*>(Zb + off) = f2bf2(v0, v1);
                }
            }
        }
    }
}

// ------------------------- kernels -----------------------------------------

// multi-problem dense GEMM (z picks problem)
__global__ void __launch_bounds__(256) gemm_multi(
    GArg g0, GArg g1, GArg g2, GArg g3, int M, int N, int K)
{
    __shared__ uint32_t pool[POOLW];
    GArg ga = (blockIdx.z == 0) ? g0 : (blockIdx.z == 1) ? g1 : (blockIdx.z == 2) ? g2 : g3;
    dense_body(pool, ga, blockIdx.y * 128, blockIdx.x * 128, N, K, threadIdx.x);
}

// fused step3+step4: parity-interleaved gated projections + z GEMM (independent work)
__global__ void __launch_bounds__(256) step34_fused(
    GArg g1, GArg g2,
    const int* __restrict__ nidx, const bf16* __restrict__ qh,
    const bf16* __restrict__ XK, const int* __restrict__ mask, bf16* __restrict__ ZM)
{
    __shared__ uint32_t pool[POOLW];
    int bid = blockIdx.x;
    int idx = bid >> 1;
    if ((bid & 1) == 0) {
        // dense: 1024 CTAs = 2 problems x (4 x 128)
        int p = idx >> 9;
        int r = idx & 511;
        dense_body(pool, p ? g2 : g1, (r >> 2) * 128, (r & 3) * 128, DM, DM, threadIdx.x);
    } else {
        // zgemm: 1024 CTAs = 2(l) x 8(n) x 64(b)
        int bl = (idx & 1) * 128;
        int bm = ((idx >> 1) & 7) * 128;
        int b  = idx >> 4;
        zgemm_body(pool, nidx, qh, XK, mask, ZM, b, bm, bl, threadIdx.x);
    }
}

// fused prep: LN1 rows + weight/q_tab conversion, 128-thread blocks
struct CvtArgs {
    const float* s[9];
    bf16* d[9];
    int cum[10];
};
__global__ void __launch_bounds__(128) prep_fused(
    const float* __restrict__ X, const float* __restrict__ G,
    const float* __restrict__ B, bf16* __restrict__ O, CvtArgs a)
{
    __shared__ float sred[4];
    int bid = blockIdx.x;
    if (bid < M1) {
        int row = bid;
        int t = threadIdx.x;
        const float4 v = reinterpret_cast<const float4*>(X + (size_t)row * DM)[t];
        float s = v.x + v.y + v.z + v.w;
        #pragma unroll
        for (int o = 16; o; o >>= 1) s += __shfl_down_sync(0xffffffffu, s, o);
        if ((t & 31) == 0) sred[t >> 5] = s;
        __syncthreads();
        float mu = (sred[0] + sred[1] + sred[2] + sred[3]) * (1.0f / DM);
        __syncthreads();
        float4 d;
        d.x = v.x - mu; d.y = v.y - mu; d.z = v.z - mu; d.w = v.w - mu;
        float ss = d.x * d.x + d.y * d.y + d.z * d.z + d.w * d.w;
        #pragma unroll
        for (int o = 16; o; o >>= 1) ss += __shfl_down_sync(0xffffffffu, ss, o);
        if ((t & 31) == 0) sred[t >> 5] = ss;
        __syncthreads();
        float var = (sred[0] + sred[1] + sred[2] + sred[3]) * (1.0f / DM);
        float rstd = rsqrtf(var + 1e-5f);
        const float4 g4 = reinterpret_cast<const float4*>(G)[t];
        const float4 b4 = reinterpret_cast<const float4*>(B)[t];
        uint2 o;
        o.x = f2bf2(d.x * rstd * g4.x + b4.x, d.y * rstd * g4.y + b4.y);
        o.y = f2bf2(d.z * rstd * g4.z + b4.z, d.w * rstd * g4.w + b4.w);
        reinterpret_cast<uint2*>(O + (size_t)row * DM)[t] = o;
    } else {
        int i = (bid - M1) * 128 + threadIdx.x;
        if (i < a.cum[9]) {
            int t = 0;
            #pragma unroll
            for (int j = 1; j < 9; j++) t += (i >= a.cum[j]);
            int off = i - a.cum[t];
            float4 v = reinterpret_cast<const float4*>(a.s[t])[off];
            uint2 o;
            o.x = f2bf2(v.x, v.y);
            o.y = f2bf2(v.z, v.w);
            reinterpret_cast<uint2*>(a.d[t])[off] = o;
        }
    }
}

// plain LN (used for LN2)
__global__ void ln_kernel(const float* __restrict__ X, const float* __restrict__ G,
                          const float* __restrict__ B, bf16* __restrict__ O)
{
    __shared__ float sred[4];
    int row = blockIdx.x;
    int t = threadIdx.x;
    const float4 v = reinterpret_cast<const float4*>(X + (size_t)row * DM)[t];
    float s = v.x + v.y + v.z + v.w;
    #pragma unroll
    for (int o = 16; o; o >>= 1) s += __shfl_down_sync(0xffffffffu, s, o);
    if ((t & 31) == 0) sred[t >> 5] = s;
    __syncthreads();
    float mu = (sred[0] + sred[1] + sred[2] + sred[3]) * (1.0f / DM);
    __syncthreads();
    float4 d;
    d.x = v.x - mu; d.y = v.y - mu; d.z = v.z - mu; d.w = v.w - mu;
    float ss = d.x * d.x + d.y * d.y + d.z * d.z + d.w * d.w;
    #pragma unroll
    for (int o = 16; o; o >>= 1) ss += __shfl_down_sync(0xffffffffu, ss, o);
    if ((t & 31) == 0) sred[t >> 5] = ss;
    __syncthreads();
    float var = (sred[0] + sred[1] + sred[2] + sred[3]) * (1.0f / DM);
    float rstd = rsqrtf(var + 1e-5f);
    const float4 g4 = reinterpret_cast<const float4*>(G)[t];
    const float4 b4 = reinterpret_cast<const float4*>(B)[t];
    uint2 o;
    o.x = f2bf2(d.x * rstd * g4.x + b4.x, d.y * rstd * g4.y + b4.y);
    o.y = f2bf2(d.z * rstd * g4.z + b4.z, d.w * rstd * g4.w + b4.w);
    reinterpret_cast<uint2*>(O + (size_t)row * DM)[t] = o;
}

// ------------------------- fused sums on bf16 ZM ---------------------------------------------
__global__ void __launch_bounds__(256) sums_fused(
    const bf16* __restrict__ ZM,
    float* __restrict__ invA, float* __restrict__ invB,
    float* __restrict__ psA, float* __restrict__ psB)
{
    __shared__ float colA[8][LEN];
    __shared__ float colB[8][LEN];
    int b = blockIdx.x, s = blockIdx.y;
    int warp = threadIdx.x >> 5, lane = threadIdx.x & 31;
    int n0 = s * (NEXP / NSPLIT);

    float ca0[4] = {}, ca1[4] = {}, cb0[4] = {}, cb1[4] = {};

    for (int r = warp; r < NEXP / NSPLIT; r += 8) {
        int n = n0 + r;
        const uint32_t* zr = reinterpret_cast<const uint32_t*>(ZM + ((size_t)b * NEXP + n) * LEN);
        float sa = 0.f, sb = 0.f;
        #pragma unroll
        for (int c = 0; c < 4; c++) {
            uint32_t u = zr[c * 32 + lane];
            float lo = bflo(u), hi = bfhi(u);
            float fa0 = fmaxf(lo, 0.f), fa1 = fmaxf(hi, 0.f);
            float fb0 = fmaxf(-lo, 0.f), fb1 = fmaxf(-hi, 0.f);
            sa += fa0 + fa1; sb += fb0 + fb1;
            ca0[c] += fa0; ca1[c] += fa1;
            cb0[c] += fb0; cb1[c] += fb1;
        }
        #pragma unroll
        for (int o = 16; o; o >>= 1) {
            sa += __shfl_down_sync(0xffffffffu, sa, o);
            sb += __shfl_down_sync(0xffffffffu, sb, o);
        }
        if (!lane) {
            invA[b * NEXP + n] = 1.f / (sa + 1e-9f);
            invB[b * NEXP + n] = 1.f / (sb + 1e-9f);
        }
    }
    #pragma unroll
    for (int c = 0; c < 4; c++) {
        colA[warp][c * 64 + 2 * lane]     = ca0[c];
        colA[warp][c * 64 + 2 * lane + 1] = ca1[c];
        colB[warp][c * 64 + 2 * lane]     = cb0[c];
        colB[warp][c * 64 + 2 * lane + 1] = cb1[c];
    }
    __syncthreads();
    int l = threadIdx.x;
    float sa = 0.f, sb = 0.f;
    #pragma unroll
    for (int w = 0; w < 8; w++) { sa += colA[w][l]; sb += colB[w][l]; }
    psA[((size_t)b * NSPLIT + s) * LEN + l] = sa;
    psB[((size_t)b * NSPLIT + s) * LEN + l] = sb;
}

__global__ void bw_final(const float* __restrict__ psA, const float* __restrict__ psB,
                         float* __restrict__ invA, float* __restrict__ invB)
{
    int b = blockIdx.x, l = threadIdx.x;
    float sa = 0.f, sb = 0.f;
    for (int s = 0; s < NSPLIT; s++) {
        sa += psA[((size_t)b * NSPLIT + s) * LEN + l];
        sb += psB[((size_t)b * NSPLIT + s) * LEN + l];
    }
    invA[b * LEN + l] = 1.f / (sa + 1e-9f);
    invB[b * LEN + l] = 1.f / (sb + 1e-9f);
}

// ------------------------- forward class GEMM (mma.sync dual) --------------------------------
__global__ void __launch_bounds__(256) classfw_bf16(
    const bf16* __restrict__ ZM,
    const bf16* __restrict__ AE, const bf16* __restrict__ BE,
    const float* __restrict__ invA, const float* __restrict__ invB,
    const int* __restrict__ nidx, const float* __restrict__ btab,
    bf16* __restrict__ CA, bf16* __restrict__ CB)
{
    __shared__ uint32_t sm[2][CF_STAGE];
    int tid = threadIdx.x;
    int b  = blockIdx.z;
    int bm = blockIdx.y * 128;
    int bn = blockIdx.x * 64;
    int warp = tid >> 5, lane = tid & 31;
    int wr = warp >> 1, wc = warp & 1;
    int g = lane >> 2, t4 = lane & 3;

    float acca[2][4][4] = {}, accb[2][4][4] = {};

    int anr = tid >> 1, alc8 = (tid & 1) * 8, alc2 = (tid & 1) * 4;
    int bl2 = tid >> 5, bdc = lane * 2;
    uint4 za; uint32_t rE0, rE1, rB0, rB1;

    auto loadregs = [&](int k0) {
        int n = bm + anr; if (n >= NEXP) n = NEXP - 1;
        za = *reinterpret_cast<const uint4*>(ZM + ((size_t)b * NEXP + n) * LEN + k0 + alc8);
        size_t e0 = ((size_t)b * LEN + k0 + 2 * bl2) * DM + bn + bdc;
        size_t e1 = e0 + DM;
        rE0 = *reinterpret_cast<const uint32_t*>(AE + e0);
        rE1 = *reinterpret_cast<const uint32_t*>(AE + e1);
        rB0 = *reinterpret_cast<const uint32_t*>(BE + e0);
        rB1 = *reinterpret_cast<const uint32_t*>(BE + e1);
    };
    auto storeregs = [&](int s) {
        uint32_t* Aa = &sm[s][0];
        uint32_t* Ab = &sm[s][CF_AB];
        uint32_t* Ba = &sm[s][2 * CF_AB];
        uint32_t* Bb = &sm[s][2 * CF_AB + CF_B];
        uint4 ua, ub;
        ua.x = bfrelu2(za.x); ub.x = bfrelu2(bfneg2(za.x));
        ua.y = bfrelu2(za.y); ub.y = bfrelu2(bfneg2(za.y));
        ua.z = bfrelu2(za.z); ub.z = bfrelu2(bfneg2(za.z));
        ua.w = bfrelu2(za.w); ub.w = bfrelu2(bfneg2(za.w));
        *reinterpret_cast<uint4*>(&Aa[anr * AFST + alc2]) = ua;
        *reinterpret_cast<uint4*>(&Ab[anr * AFST + alc2]) = ub;
        Ba[bl2 * BCST + bdc]     = __byte_perm(rE0, rE1, 0x5410);
        Ba[bl2 * BCST + bdc + 1] = __byte_perm(rE0, rE1, 0x7632);
        Bb[bl2 * BCST + bdc]     = __byte_perm(rB0, rB1, 0x5410);
        Bb[bl2 * BCST + bdc + 1] = __byte_perm(rB0, rB1, 0x7632);
    };
    auto compute = [&](int s) {
        const uint32_t* Aa = &sm[s][0];
        const uint32_t* Ab = &sm[s][CF_AB];
        const uint32_t* Ba = &sm[s][2 * CF_AB];
        const uint32_t* Bb = &sm[s][2 * CF_AB + CF_B];
        uint32_t afa[2][4], afb[2][4], bfa[4][2], bfb[4][2];
        #pragma unroll
        for (int c = 0; c < 2; c++) {
            int row = wr * 32 + c * 16 + g;
            afa[c][0] = Aa[row * AFST + t4];
            afa[c][1] = Aa[(row + 8) * AFST + t4];
            afa[c][2] = Aa[row * AFST + t4 + 4];
            afa[c][3] = Aa[(row + 8) * AFST + t4 + 4];
            afb[c][0] = Ab[row * AFST + t4];
            afb[c][1] = Ab[(row + 8) * AFST + t4];
            afb[c][2] = Ab[row * AFST + t4 + 4];
            afb[c][3] = Ab[(row + 8) * AFST + t4 + 4];
        }
        #pragma unroll
        for (int nb = 0; nb < 4; nb++) {
            int col = wc * 32 + nb * 8 + g;
            bfa[nb][0] = Ba[t4 * BCST + col];
            bfa[nb][1] = Ba[(t4 + 4) * BCST + col];
            bfb[nb][0] = Bb[t4 * BCST + col];
            bfb[nb][1] = Bb[(t4 + 4) * BCST + col];
        }
        #pragma unroll
        for (int c = 0; c < 2; c++)
            #pragma unroll
            for (int nb = 0; nb < 4; nb++) {
                mma16(acca[c][nb], afa[c], bfa[nb]);
                mma16(accb[c][nb], afb[c], bfb[nb]);
            }
    };

    loadregs(0);
    storeregs(0);
    __syncthreads();
    const int KT = LEN / 16;
    for (int t = 0; t < KT; t++) {
        if (t + 1 < KT) loadregs((t + 1) * 16);
        compute(t & 1);
        if (t + 1 < KT) storeregs((t + 1) & 1);
        __syncthreads();
    }

    #pragma unroll
    for (int c = 0; c < 2; c++) {
        #pragma unroll
        for (int h = 0; h < 2; h++) {
            int n = bm + wr * 32 + c * 16 + g + h * 8;
            if (n >= NEXP) continue;
            float ia = invA[b * NEXP + n];
            float ib = invB[b * NEXP + n];
            int qi = nidx[b * NEXP + n];
            #pragma unroll
            for (int nb = 0; nb < 4; nb++) {
                int d0 = bn + wc * 32 + nb * 8 + 2 * t4;
                float2 bi = *reinterpret_cast<const float2*>(btab + (size_t)qi * DM + d0);
                size_t off = ((size_t)b * NEXP + n) * DM + d0;
                *reinterpret_cast<uint32_t*>(CA + off) =
                    f2bf2(acca[c][nb][h * 2 + 0] * ia + bi.x,
                          acca[c][nb][h * 2 + 1] * ia + bi.y);
                *reinterpret_cast<uint32_t*>(CB + off) =
                    f2bf2(accb[c][nb][h * 2 + 0] * ib + bi.x,
                          accb[c][nb][h * 2 + 1] * ib + bi.y);
            }
        }
    }
}

// ------------------------- backward class GEMM (mma.sync dual) -------------------------------
__global__ void __launch_bounds__(256) classbw_bf16(
    const bf16* __restrict__ ZM,
    const bf16* __restrict__ CA, const bf16* __restrict__ CB,
    const float* __restrict__ invA, const float* __restrict__ invB,
    const float* __restrict__ SELp, const float* __restrict__ X,
    float* __restrict__ X1)
{
    __shared__ uint32_t sm[2][CB_STAGE];
    int tid = threadIdx.x;
    int b  = blockIdx.z;
    int bl = blockIdx.y * 128;
    int bn = blockIdx.x * 64;
    int warp = tid >> 5, lane = tid & 31;
    int wr = warp >> 1, wc = warp & 1;
    int g = lane >> 2, t4 = lane & 3;

    float acca[2][4][4] = {}, accb[2][4][4] = {};

    int n2 = tid >> 5, l4 = lane * 4;
    int bdc = lane * 2;
    uint2 ze, zo; uint32_t rC0, rC1, rD0, rD1;

    auto loadregs = [&](int k0) {
        size_t z0 = ((size_t)b * NEXP + k0 + 2 * n2) * LEN + bl + l4;
        ze = *reinterpret_cast<const uint2*>(ZM + z0);
        zo = *reinterpret_cast<const uint2*>(ZM + z0 + LEN);
        size_t c0 = ((size_t)b * NEXP + k0 + 2 * n2) * DM + bn + bdc;
        size_t c1 = c0 + DM;
        rC0 = *reinterpret_cast<const uint32_t*>(CA + c0);
        rC1 = *reinterpret_cast<const uint32_t*>(CA + c1);
        rD0 = *reinterpret_cast<const uint32_t*>(CB + c0);
        rD1 = *reinterpret_cast<const uint32_t*>(CB + c1);
    };
    auto storeregs = [&](int s) {
        uint32_t* Aa = &sm[s][0];
        uint32_t* Ab = &sm[s][CB_AB];
        uint32_t* Ba = &sm[s][2 * CB_AB];
        uint32_t* Bb = &sm[s][2 * CB_AB + CF_B];
        uint32_t p[4];
        p[0] = __byte_perm(ze.x, zo.x, 0x5410);
        p[1] = __byte_perm(ze.x, zo.x, 0x7632);
        p[2] = __byte_perm(ze.y, zo.y, 0x5410);
        p[3] = __byte_perm(ze.y, zo.y, 0x7632);
        #pragma unroll
        for (int i = 0; i < 4; i++) {
            Aa[(l4 + i) * ABST + n2] = bfrelu2(p[i]);
            Ab[(l4 + i) * ABST + n2] = bfrelu2(bfneg2(p[i]));
        }
        Ba[n2 * BCST + bdc]     = __byte_perm(rC0, rC1, 0x5410);
        Ba[n2 * BCST + bdc + 1] = __byte_perm(rC0, rC1, 0x7632);
        Bb[n2 * BCST + bdc]     = __byte_perm(rD0, rD1, 0x5410);
        Bb[n2 * BCST + bdc + 1] = __byte_perm(rD0, rD1, 0x7632);
    };
    auto compute = [&](int s) {
        const uint32_t* Aa = &sm[s][0];
        const uint32_t* Ab = &sm[s][CB_AB];
        const uint32_t* Ba = &sm[s][2 * CB_AB];
        const uint32_t* Bb = &sm[s][2 * CB_AB + CF_B];
        uint32_t afa[2][4], afb[2][4], bfa[4][2], bfb[4][2];
        #pragma unroll
        for (int c = 0; c < 2; c++) {
            int row = wr * 32 + c * 16 + g;
            afa[c][0] = Aa[row * ABST + t4];
            afa[c][1] = Aa[(row + 8) * ABST + t4];
            afa[c][2] = Aa[row * ABST + t4 + 4];
            afa[c][3] = Aa[(row + 8) * ABST + t4 + 4];
            afb[c][0] = Ab[row * ABST + t4];
            afb[c][1] = Ab[(row + 8) * ABST + t4];
            afb[c][2] = Ab[row * ABST + t4 + 4];
            afb[c][3] = Ab[(row + 8) * ABST + t4 + 4];
        }
        #pragma unroll
        for (int nb = 0; nb < 4; nb++) {
            int col = wc * 32 + nb * 8 + g;
            bfa[nb][0] = Ba[t4 * BCST + col];
            bfa[nb][1] = Ba[(t4 + 4) * BCST + col];
            bfb[nb][0] = Bb[t4 * BCST + col];
            bfb[nb][1] = Bb[(t4 + 4) * BCST + col];
        }
        #pragma unroll
        for (int c = 0; c < 2; c++)
            #pragma unroll
            for (int nb = 0; nb < 4; nb++) {
                mma16(acca[c][nb], afa[c], bfa[nb]);
                mma16(accb[c][nb], afb[c], bfb[nb]);
            }
    };

    loadregs(0);
    storeregs(0);
    __syncthreads();
    const int KT = NEXP / 16;
    for (int t = 0; t < KT; t++) {
        if (t + 1 < KT) loadregs((t + 1) * 16);
        compute(t & 1);
        if (t + 1 < KT) storeregs((t + 1) & 1);
        __syncthreads();
    }

    #pragma unroll
    for (int c = 0; c < 2; c++) {
        #pragma unroll
        for (int h = 0; h < 2; h++) {
            int l = bl + wr * 32 + c * 16 + g + h * 8;
            float ia = invA[b * LEN + l];
            float ib = invB[b * LEN + l];
            #pragma unroll
            for (int nb = 0; nb < 4; nb++) {
                int d0 = bn + wc * 32 + nb * 8 + 2 * t4;
                size_t off = ((size_t)b * LEN + l) * DM + d0;
                float2 s2 = *reinterpret_cast<const float2*>(SELp + off);
                float2 x2 = *reinterpret_cast<const float2*>(X + off);
                float2 o;
                o.x = x2.x + s2.x * (acca[c][nb][h * 2 + 0] * ia)
                           + (1.f - s2.x) * (accb[c][nb][h * 2 + 0] * ib);
                o.y = x2.y + s2.y * (acca[c][nb][h * 2 + 1] * ia)
                           + (1.f - s2.y) * (accb[c][nb][h * 2 + 1] * ib);
                *reinterpret_cast<float2*>(X1 + off) = o;
            }
        }
    }
}

// ------------------------- launch -------------------------
extern "C" void kernel_launch(void* const* d_in, const int* in_sizes, int n_in,
                              void* d_out, int out_size)
{
    const float* x     = (const float*)d_in[0];
    const int*   nidx  = (const int*)d_in[1];
    const int*   mask  = (const int*)d_in[2];
    const float* ln1_g = (const float*)d_in[3];
    const float* ln1_b = (const float*)d_in[4];
    const float* ln2_g = (const float*)d_in[5];
    const float* ln2_b = (const float*)d_in[6];
    const float* q_tab = (const float*)d_in[7];
    const float* b_tab = (const float*)d_in[8];
    const float* Wk  = (const float*)d_in[9];  const float* bk   = (const float*)d_in[10];
    const float* Wa  = (const float*)d_in[11]; const float* ba   = (const float*)d_in[12];
    const float* Wa1 = (const float*)d_in[13]; const float* ba1  = (const float*)d_in[14];
    const float* Wb  = (const float*)d_in[15]; const float* bb   = (const float*)d_in[16];
    const float* Wb1 = (const float*)d_in[17]; const float* bb1  = (const float*)d_in[18];
    const float* Ws  = (const float*)d_in[19]; const float* bsel = (const float*)d_in[20];
    const float* Wf1 = (const float*)d_in[21]; const float* bf1  = (const float*)d_in[22];
    const float* Wf2 = (const float*)d_in[23]; const float* bf2  = (const float*)d_in[24];
    float* out = (float*)d_out;

    bf16 *pX2, *pXK, *pEA0, *pEB0, *pAE, *pBE, *pZM, *pCA, *pCB, *pH, *pWH, *pQH;
    float *pSEL, *pX1, *pIAf, *pIBf, *pPA, *pPB, *pIAb, *pIBb;
    cudaGetSymbolAddress((void**)&pX2, g_X2);
    cudaGetSymbolAddress((void**)&pXK, g_XK);
    cudaGetSymbolAddress((void**)&pEA0, g_EA0);
    cudaGetSymbolAddress((void**)&pEB0, g_EB0);
    cudaGetSymbolAddress((void**)&pAE, g_AE);
    cudaGetSymbolAddress((void**)&pBE, g_BE);
    cudaGetSymbolAddress((void**)&pSEL, g_SEL);
    cudaGetSymbolAddress((void**)&pX1, g_X1);
    cudaGetSymbolAddress((void**)&pZM, g_ZM);
    cudaGetSymbolAddress((void**)&pCA, g_CA);
    cudaGetSymbolAddress((void**)&pCB, g_CB);
    cudaGetSymbolAddress((void**)&pH, g_H);
    cudaGetSymbolAddress((void**)&pIAf, g_IAf);
    cudaGetSymbolAddress((void**)&pIBf, g_IBf);
    cudaGetSymbolAddress((void**)&pPA, g_PA);
    cudaGetSymbolAddress((void**)&pPB, g_PB);
    cudaGetSymbolAddress((void**)&pIAb, g_IAb);
    cudaGetSymbolAddress((void**)&pIBb, g_IBb);
    cudaGetSymbolAddress((void**)&pWH, g_WH);
    cudaGetSymbolAddress((void**)&pQH, g_QH);

    bf16* WkH  = pWH;
    bf16* WaH  = pWH + 262144;
    bf16* WbH  = pWH + 524288;
    bf16* WsH  = pWH + 786432;
    bf16* Wa1H = pWH + 1048576;
    bf16* Wb1H = pWH + 1310720;
    bf16* Wf1H = pWH + 1572864;
    bf16* Wf2H = pWH + 2621440;

    // 0. fused LN1 + weight conversion (1 launch, 128-thread blocks)
    CvtArgs ca;
    ca.s[0] = Wk;  ca.d[0] = WkH;
    ca.s[1] = Wa;  ca.d[1] = WaH;
    ca.s[2] = Wb;  ca.d[2] = WbH;
    ca.s[3] = Ws;  ca.d[3] = WsH;
    ca.s[4] = Wa1; ca.d[4] = Wa1H;
    ca.s[5] = Wb1; ca.d[5] = Wb1H;
    ca.s[6] = Wf1; ca.d[6] = Wf1H;
    ca.s[7] = Wf2; ca.d[7] = Wf2H;
    ca.s[8] = q_tab; ca.d[8] = pQH;
    int sizes4[9] = {65536, 65536, 65536, 65536, 65536, 65536, 262144, 262144, 126976};
    ca.cum[0] = 0;
    for (int i = 0; i < 9; i++) ca.cum[i + 1] = ca.cum[i] + sizes4[i];
    int cvtBlocks = (ca.cum[9] + 127) / 128;
    prep_fused<<<M1 + cvtBlocks, 128>>>(x, ln1_g, ln1_b, pX2, ca);

    // 1. merged dense projections {Wk, Wa, Wb, Ws}
    GArg gk = {pX2, WkH, bk,   nullptr, pXK,  0};
    GArg ga_ = {pX2, WaH, ba,  nullptr, pEA0, 0};
    GArg gb = {pX2, WbH, bb,   nullptr, pEB0, 0};
    GArg gs = {pX2, WsH, bsel, nullptr, pSEL, 1};
    gemm_multi<<<dim3(DM / 128, M1 / 128, 4), 256>>>(gk, ga_, gb, gs, M1, DM, DM);

    // 2. fused step3+4: gated projections {Wa1, Wb1} interleaved with z GEMM
    GArg g1 = {pEA0, Wa1H, ba1, pEA0, pAE, 3};
    GArg g2 = {pEB0, Wb1H, bb1, pEB0, pBE, 3};
    step34_fused<<<2048, 256>>>(g1, g2, nidx, pQH, pXK, mask, pZM);

    // 3. sums
    sums_fused<<<dim3(BSZ, NSPLIT), 256>>>(pZM, pIAf, pIBf, pPA, pPB);
    bw_final<<<BSZ, LEN>>>(pPA, pPB, pIAb, pIBb);

    // 4. class GEMMs
    classfw_bf16<<<dim3(DM / 64, (NEXP + 127) / 128, BSZ), 256>>>(
        pZM, pAE, pBE, pIAf, pIBf, nidx, b_tab, pCA, pCB);
    classbw_bf16<<<dim3(DM / 64, LEN / 128, BSZ), 256>>>(
        pZM, pCA, pCB, pIAb, pIBb, pSEL, x, pX1);

    // 5. LN2 + FFN
    ln_kernel<<<M1, 128>>>(pX1, ln2_g, ln2_b, pX2);
    GArg gf1 = {pX2, Wf1H, bf1, nullptr, pH, 2};
    gemm_multi<<<dim3(DFF / 128, M1 / 128, 1), 256>>>(gf1, gf1, gf1, gf1, M1, DFF, DM);
    GArg gf2 = {pH, Wf2H, bf2, pX1, out, 4};
    gemm_multi<<<dim3(DM / 128, M1 / 128, 1), 256>>>(gf2, gf2, gf2, gf2, M1, DM, DFF);
}

// round 16
// speedup vs baseline: 1.0356x; 1.0037x over previous
#include <cuda_runtime.h>
#include <cuda_bf16.h>
#include <math.h>
#include <stdint.h>

#define BSZ  64
#define LEN  256
#define DM   512
#define DFF  2048
#define NEXP 992
#define M1   (BSZ * LEN)
#define NSPLIT 8
#define ZSCALE 0.044194173824159216f   // 1/sqrt(512)

typedef __nv_bfloat16 bf16;

// ---- dense GEMM (K-tile 32) smem strides, b32 units ----
#define AST2 20
#define BST2 136
// ---- z GEMM tiling (K-tile 16) ----
#define ASTB 12
#define BSTB 136
// ---- class GEMM tiling ----
#define AFST 12
#define ABST 9
#define BCST 72
#define CF_AB 1536
#define CF_B  576
#define CF_STAGE (2 * CF_AB + 2 * CF_B)
#define CB_AB 1152
#define CB_STAGE (2 * CB_AB + 2 * CF_B)
// fused smem pool (words): dense needs 2*2560 + 2*2176 = 9472
#define POOLW 9472

// ------------------------- scratch -------------------------
static __device__ bf16  g_X2  [(size_t)M1 * DM];
static __device__ bf16  g_XK  [(size_t)M1 * DM];
static __device__ bf16  g_EA0 [(size_t)M1 * DM];
static __device__ bf16  g_EB0 [(size_t)M1 * DM];
static __device__ bf16  g_AE  [(size_t)M1 * DM];
static __device__ bf16  g_BE  [(size_t)M1 * DM];
static __device__ float g_SEL [(size_t)M1 * DM];
static __device__ float g_X1  [(size_t)M1 * DM];
static __device__ bf16  g_ZM  [(size_t)BSZ * NEXP * LEN];
static __device__ bf16  g_CA  [(size_t)BSZ * NEXP * DM];
static __device__ bf16  g_CB  [(size_t)BSZ * NEXP * DM];
static __device__ bf16  g_H   [(size_t)M1 * DFF];
static __device__ float g_IAf [BSZ * NEXP];
static __device__ float g_IBf [BSZ * NEXP];
static __device__ float g_PA  [BSZ * NSPLIT * LEN];
static __device__ float g_PB  [BSZ * NSPLIT * LEN];
static __device__ float g_IAb [BSZ * LEN];
static __device__ float g_IBb [BSZ * LEN];
static __device__ bf16  g_WH  [3670016];           // bf16 weights [K,N]
static __device__ bf16  g_QH  [(size_t)NEXP * DM]; // bf16 q_tab

// ------------------------- helpers -------------------------
__device__ __forceinline__ uint32_t f2bf2(float lo, float hi) {
    uint32_t r;
    asm("cvt.rn.bf16x2.f32 %0, %1, %2;" : "=r"(r) : "f"(hi), "f"(lo));
    return r;
}
__device__ __forceinline__ uint32_t bfrelu2(uint32_t x) {
    uint32_t r;
    asm("max.bf16x2 %0, %1, %2;" : "=r"(r) : "r"(x), "r"(0u));
    return r;
}
__device__ __forceinline__ uint32_t bfneg2(uint32_t x) { return x ^ 0x80008000u; }
__device__ __forceinline__ float bflo(uint32_t u) { return __uint_as_float(u << 16); }
__device__ __forceinline__ float bfhi(uint32_t u) { return __uint_as_float(u & 0xffff0000u); }

__device__ __forceinline__ void mma16(float* d, const uint32_t* a, const uint32_t* b) {
    asm volatile(
        "mma.sync.aligned.m16n8k16.row.col.f32.bf16.bf16.f32 "
        "{%0,%1,%2,%3}, {%4,%5,%6,%7}, {%8,%9}, {%0,%1,%2,%3};"
        : "+f"(d[0]), "+f"(d[1]), "+f"(d[2]), "+f"(d[3])
        : "r"(a[0]), "r"(a[1]), "r"(a[2]), "r"(a[3]), "r"(b[0]), "r"(b[1]));
}

struct GArg {
    const bf16* A;
    const bf16* B;     // [K,N] row-major
    const float* bias;
    const void* Dm;
    void* C;
    int mode;
};

// ------------------------- shared GEMM bodies --------------------------------
// dense 128x128, K-tile 32
__device__ __forceinline__ void dense_body(
    uint32_t* pool, const GArg& ga, int bm, int bn, int N, int K, int tid)
{
    uint32_t* AsU0 = pool;                 // stage stride 2560
    uint32_t* BsU0 = pool + 2 * 2560;      // stage stride 2176

    int warp = tid >> 5, lane = tid & 31;
    int wr = warp >> 1, wc = warp & 1;
    int g = lane >> 2, t4 = lane & 3;

    int arow = tid >> 1, ah16 = (tid & 1) * 16, ah8 = (tid & 1) * 8;
    int bw = tid >> 5, bc = lane * 4;

    float acc[2][8][4];
    #pragma unroll
    for (int c = 0; c < 2; c++)
        #pragma unroll
        for (int nb = 0; nb < 8; nb++)
            #pragma unroll
            for (int i = 0; i < 4; i++) acc[c][nb][i] = 0.f;

    int KT = K / 32;
    uint4 ra0, ra1;
    uint2 rb[2][2];

    auto loadregs = [&](int k0) {
        const bf16* Ap = ga.A + (size_t)(bm + arow) * K + k0 + ah16;
        ra0 = *reinterpret_cast<const uint4*>(Ap);
        ra1 = *reinterpret_cast<const uint4*>(Ap + 8);
        int krA = k0 + 2 * bw;
        rb[0][0] = *reinterpret_cast<const uint2*>(ga.B + (size_t)krA * N + bn + bc);
        rb[0][1] = *reinterpret_cast<const uint2*>(ga.B + (size_t)(krA + 1) * N + bn + bc);
        int krB = k0 + 2 * (bw + 8);
        rb[1][0] = *reinterpret_cast<const uint2*>(ga.B + (size_t)krB * N + bn + bc);
        rb[1][1] = *reinterpret_cast<const uint2*>(ga.B + (size_t)(krB + 1) * N + bn + bc);
    };
    auto storeregs = [&](int s) {
        uint32_t* ap = &AsU0[s * 2560 + arow * AST2 + ah8];
        *reinterpret_cast<uint4*>(ap) = ra0;
        *reinterpret_cast<uint4*>(ap + 4) = ra1;
        uint32_t* bp0 = &BsU0[s * 2176 + bw * BST2 + bc];
        bp0[0] = __byte_perm(rb[0][0].x, rb[0][1].x, 0x5410);
        bp0[1] = __byte_perm(rb[0][0].x, rb[0][1].x, 0x7632);
        bp0[2] = __byte_perm(rb[0][0].y, rb[0][1].y, 0x5410);
        bp0[3] = __byte_perm(rb[0][0].y, rb[0][1].y, 0x7632);
        uint32_t* bp1 = &BsU0[s * 2176 + (bw + 8) * BST2 + bc];
        bp1[0] = __byte_perm(rb[1][0].x, rb[1][1].x, 0x5410);
        bp1[1] = __byte_perm(rb[1][0].x, rb[1][1].x, 0x7632);
        bp1[2] = __byte_perm(rb[1][0].y, rb[1][1].y, 0x5410);
        bp1[3] = __byte_perm(rb[1][0].y, rb[1][1].y, 0x7632);
    };
    auto compute = [&](int s, int h) {
        uint32_t a[2][4], b[8][2];
        #pragma unroll
        for (int c = 0; c < 2; c++) {
            int row = wr * 32 + c * 16 + g;
            const uint32_t* ap = &AsU0[s * 2560 + row * AST2 + h * 8];
            a[c][0] = ap[t4];
            a[c][1] = ap[8 * AST2 + t4];
            a[c][2] = ap[t4 + 4];
            a[c][3] = ap[8 * AST2 + t4 + 4];
        }
        #pragma unroll
        for (int nb = 0; nb < 8; nb++) {
            int col = wc * 64 + nb * 8 + g;
            b[nb][0] = BsU0[s * 2176 + (h * 8 + t4) * BST2 + col];
            b[nb][1] = BsU0[s * 2176 + (h * 8 + t4 + 4) * BST2 + col];
        }
        #pragma unroll
        for (int c = 0; c < 2; c++)
            #pragma unroll
            for (int nb = 0; nb < 8; nb++)
                mma16(acc[c][nb], a[c], b[nb]);
    };

    loadregs(0);
    storeregs(0);
    __syncthreads();
    for (int t = 0; t < KT; t++) {
        if (t + 1 < KT) loadregs((t + 1) * 32);
        compute(t & 1, 0);
        compute(t & 1, 1);
        if (t + 1 < KT) storeregs((t + 1) & 1);
        __syncthreads();
    }

    int mode = ga.mode;
    #pragma unroll
    for (int c = 0; c < 2; c++) {
        #pragma unroll
        for (int nb = 0; nb < 8; nb++) {
            int n = bn + wc * 64 + nb * 8 + 2 * t4;
            float2 bi = *reinterpret_cast<const float2*>(ga.bias + n);
            #pragma unroll
            for (int h = 0; h < 2; h++) {
                int m = bm + wr * 32 + c * 16 + g + h * 8;
                size_t off = (size_t)m * N + n;
                float v0 = acc[c][nb][h * 2 + 0] + bi.x;
                float v1 = acc[c][nb][h * 2 + 1] + bi.y;
                if (mode == 1) {
                    v0 = 1.f / (1.f + expf(-v0)); v1 = 1.f / (1.f + expf(-v1));
                    *reinterpret_cast<float2*>((float*)ga.C + off) = make_float2(v0, v1);
                } else if (mode == 4) {
                    float2 d2 = *reinterpret_cast<const float2*>((const float*)ga.Dm + off);
                    *reinterpret_cast<float2*>((float*)ga.C + off) = make_float2(v0 + d2.x, v1 + d2.y);
                } else {
                    if (mode == 2) {
                        v0 = fmaxf(v0, 0.f); v1 = fmaxf(v1, 0.f);
                    } else if (mode == 3) {
                        uint32_t du = *reinterpret_cast<const uint32_t*>((const bf16*)ga.Dm + off);
                        v0 = bflo(du) / (1.f + expf(-v0));
                        v1 = bfhi(du) / (1.f + expf(-v1));
                    }
                    *reinterpret_cast<uint32_t*>((bf16*)ga.C + off) = f2bf2(v0, v1);
                }
            }
        }
    }
}

__device__ __forceinline__ void zgemm_body(
    uint32_t* pool, const int* nidx, const bf16* qh, const bf16* XK,
    const int* mask, bf16* ZM, int b, int bm, int bl, int tid)
{
    uint32_t* AsU0 = pool;                 // stage stride 1536
    uint32_t* BsU0 = pool + 2 * 1536;      // stage stride 1088
    int* sidx = reinterpret_cast<int*>(pool + 2 * 1536 + 2 * 1088);

    int warp = tid >> 5, lane = tid & 31;
    int wr = warp >> 1, wc = warp & 1;
    int g = lane >> 2, t4 = lane & 3;

    if (tid < 128) {
        int n = bm + tid;
        sidx[tid] = nidx[b * NEXP + (n < NEXP ? n : NEXP - 1)];
    }
    __syncthreads();

    float acc[2][8][4];
    #pragma unroll
    for (int c = 0; c < 2; c++)
        #pragma unroll
        for (int nb = 0; nb < 8; nb++)
            #pragma unroll
            for (int i = 0; i < 4; i++) acc[c][nb][i] = 0.f;

    int arow = tid >> 1, ac8 = (tid & 1) * 8, ac2 = (tid & 1) * 4;
    uint4 ra, rbv;
    auto loadregs = [&](int k0) {
        ra  = *reinterpret_cast<const uint4*>(qh + (size_t)sidx[arow] * DM + k0 + ac8);
        rbv = *reinterpret_cast<const uint4*>(XK + (size_t)(b * LEN + bl + arow) * DM + k0 + ac8);
    };
    auto storeregs = [&](int s) {
        *reinterpret_cast<uint4*>(&AsU0[s * 1536 + arow * ASTB + ac2]) = ra;
        BsU0[s * 1088 + (ac2 + 0) * BSTB + arow] = rbv.x;
        BsU0[s * 1088 + (ac2 + 1) * BSTB + arow] = rbv.y;
        BsU0[s * 1088 + (ac2 + 2) * BSTB + arow] = rbv.z;
        BsU0[s * 1088 + (ac2 + 3) * BSTB + arow] = rbv.w;
    };
    auto compute = [&](int s) {
        uint32_t a[2][4], bfr[8][2];
        #pragma unroll
        for (int c = 0; c < 2; c++) {
            int row = wr * 32 + c * 16 + g;
            a[c][0] = AsU0[s * 1536 + row * ASTB + t4];
            a[c][1] = AsU0[s * 1536 + (row + 8) * ASTB + t4];
            a[c][2] = AsU0[s * 1536 + row * ASTB + t4 + 4];
            a[c][3] = AsU0[s * 1536 + (row + 8) * ASTB + t4 + 4];
        }
        #pragma unroll
        for (int nb = 0; nb < 8; nb++) {
            int col = wc * 64 + nb * 8 + g;
            bfr[nb][0] = BsU0[s * 1088 + t4 * BSTB + col];
            bfr[nb][1] = BsU0[s * 1088 + (t4 + 4) * BSTB + col];
        }
        #pragma unroll
        for (int c = 0; c < 2; c++)
            #pragma unroll
            for (int nb = 0; nb < 8; nb++)
                mma16(acc[c][nb], a[c], bfr[nb]);
    };

    int KT = DM / 16;
    loadregs(0);
    storeregs(0);
    __syncthreads();
    for (int t = 0; t < KT; t++) {
        if (t + 1 < KT) loadregs((t + 1) * 16);
        compute(t & 1);
        if (t + 1 < KT) storeregs((t + 1) & 1);
        __syncthreads();
    }

    bf16* Zb = ZM + (size_t)b * NEXP * LEN;
    const int* Mb = mask + (size_t)b * NEXP * LEN;
    #pragma unroll
    for (int c = 0; c < 2; c++) {
        #pragma unroll
        for (int nb = 0; nb < 8; nb++) {
            int l = bl + wc * 64 + nb * 8 + 2 * t4;
            #pragma unroll
            for (int h = 0; h < 2; h++) {
                int n = bm + wr * 32 + c * 16 + g + h * 8;
                if (n < NEXP) {
                    size_t off = (size_t)n * LEN + l;
                    int2 m2 = *reinterpret_cast<const int2*>(Mb + off);
                    float v0 = m2.x ? acc[c][nb][h * 2 + 0] * ZSCALE : 0.f;
                    float v1 = m2.y ? acc[c][nb][h * 2 + 1] * ZSCALE : 0.f;
                    *reinterpret_cast<uint32_t*>(Zb + off) = f2bf2(v0, v1);
                }
            }
        }
    }
}

// ------------------------- kernels -----------------------------------------

// multi-problem dense GEMM (z picks problem)
__global__ void __launch_bounds__(256) gemm_multi(
    GArg g0, GArg g1, GArg g2, GArg g3, int M, int N, int K)
{
    __shared__ uint32_t pool[POOLW];
    GArg ga = (blockIdx.z == 0) ? g0 : (blockIdx.z == 1) ? g1 : (blockIdx.z == 2) ? g2 : g3;
    dense_body(pool, ga, blockIdx.y * 128, blockIdx.x * 128, N, K, threadIdx.x);
}

// fused step3+step4: parity-interleaved gated projections + z GEMM (independent work)
__global__ void __launch_bounds__(256) step34_fused(
    GArg g1, GArg g2,
    const int* __restrict__ nidx, const bf16* __restrict__ qh,
    const bf16* __restrict__ XK, const int* __restrict__ mask, bf16* __restrict__ ZM)
{
    __shared__ uint32_t pool[POOLW];
    int bid = blockIdx.x;
    int idx = bid >> 1;
    if ((bid & 1) == 0) {
        // dense: 1024 CTAs = 2 problems x (4 x 128)
        int p = idx >> 9;
        int r = idx & 511;
        dense_body(pool, p ? g2 : g1, (r >> 2) * 128, (r & 3) * 128, DM, DM, threadIdx.x);
    } else {
        // zgemm: 1024 CTAs = 2(l) x 8(n) x 64(b)
        int bl = (idx & 1) * 128;
        int bm = ((idx >> 1) & 7) * 128;
        int b  = idx >> 4;
        zgemm_body(pool, nidx, qh, XK, mask, ZM, b, bm, bl, threadIdx.x);
    }
}

// fused prep: LN1 rows + weight/q_tab conversion, 128-thread blocks
struct CvtArgs {
    const float* s[9];
    bf16* d[9];
    int cum[10];
};
__global__ void __launch_bounds__(128) prep_fused(
    const float* __restrict__ X, const float* __restrict__ G,
    const float* __restrict__ B, bf16* __restrict__ O, CvtArgs a)
{
    __shared__ float sred[4];
    int bid = blockIdx.x;
    if (bid < M1) {
        int row = bid;
        int t = threadIdx.x;
        const float4 v = reinterpret_cast<const float4*>(X + (size_t)row * DM)[t];
        float s = v.x + v.y + v.z + v.w;
        #pragma unroll
        for (int o = 16; o; o >>= 1) s += __shfl_down_sync(0xffffffffu, s, o);
        if ((t & 31) == 0) sred[t >> 5] = s;
        __syncthreads();
        float mu = (sred[0] + sred[1] + sred[2] + sred[3]) * (1.0f / DM);
        __syncthreads();
        float4 d;
        d.x = v.x - mu; d.y = v.y - mu; d.z = v.z - mu; d.w = v.w - mu;
        float ss = d.x * d.x + d.y * d.y + d.z * d.z + d.w * d.w;
        #pragma unroll
        for (int o = 16; o; o >>= 1) ss += __shfl_down_sync(0xffffffffu, ss, o);
        if ((t & 31) == 0) sred[t >> 5] = ss;
        __syncthreads();
        float var = (sred[0] + sred[1] + sred[2] + sred[3]) * (1.0f / DM);
        float rstd = rsqrtf(var + 1e-5f);
        const float4 g4 = reinterpret_cast<const float4*>(G)[t];
        const float4 b4 = reinterpret_cast<const float4*>(B)[t];
        uint2 o;
        o.x = f2bf2(d.x * rstd * g4.x + b4.x, d.y * rstd * g4.y + b4.y);
        o.y = f2bf2(d.z * rstd * g4.z + b4.z, d.w * rstd * g4.w + b4.w);
        reinterpret_cast<uint2*>(O + (size_t)row * DM)[t] = o;
    } else {
        int i = (bid - M1) * 128 + threadIdx.x;
        if (i < a.cum[9]) {
            int t = 0;
            #pragma unroll
            for (int j = 1; j < 9; j++) t += (i >= a.cum[j]);
            int off = i - a.cum[t];
            float4 v = reinterpret_cast<const float4*>(a.s[t])[off];
            uint2 o;
            o.x = f2bf2(v.x, v.y);
            o.y = f2bf2(v.z, v.w);
            reinterpret_cast<uint2*>(a.d[t])[off] = o;
        }
    }
}

// plain LN (used for LN2)
__global__ void ln_kernel(const float* __restrict__ X, const float* __restrict__ G,
                          const float* __restrict__ B, bf16* __restrict__ O)
{
    __shared__ float sred[4];
    int row = blockIdx.x;
    int t = threadIdx.x;
    const float4 v = reinterpret_cast<const float4*>(X + (size_t)row * DM)[t];
    float s = v.x + v.y + v.z + v.w;
    #pragma unroll
    for (int o = 16; o; o >>= 1) s += __shfl_down_sync(0xffffffffu, s, o);
    if ((t & 31) == 0) sred[t >> 5] = s;
    __syncthreads();
    float mu = (sred[0] + sred[1] + sred[2] + sred[3]) * (1.0f / DM);
    __syncthreads();
    float4 d;
    d.x = v.x - mu; d.y = v.y - mu; d.z = v.z - mu; d.w = v.w - mu;
    float ss = d.x * d.x + d.y * d.y + d.z * d.z + d.w * d.w;
    #pragma unroll
    for (int o = 16; o; o >>= 1) ss += __shfl_down_sync(0xffffffffu, ss, o);
    if ((t & 31) == 0) sred[t >> 5] = ss;
    __syncthreads();
    float var = (sred[0] + sred[1] + sred[2] + sred[3]) * (1.0f / DM);
    float rstd = rsqrtf(var + 1e-5f);
    const float4 g4 = reinterpret_cast<const float4*>(G)[t];
    const float4 b4 = reinterpret_cast<const float4*>(B)[t];
    uint2 o;
    o.x = f2bf2(d.x * rstd * g4.x + b4.x, d.y * rstd * g4.y + b4.y);
    o.y = f2bf2(d.z * rstd * g4.z + b4.z, d.w * rstd * g4.w + b4.w);
    reinterpret_cast<uint2*>(O + (size_t)row * DM)[t] = o;
}

// ------------------------- fused sums on bf16 ZM ---------------------------------------------
__global__ void __launch_bounds__(256) sums_fused(
    const bf16* __restrict__ ZM,
    float* __restrict__ invA, float* __restrict__ invB,
    float* __restrict__ psA, float* __restrict__ psB)
{
    __shared__ float colA[8][LEN];
    __shared__ float colB[8][LEN];
    int b = blockIdx.x, s = blockIdx.y;
    int warp = threadIdx.x >> 5, lane = threadIdx.x & 31;
    int n0 = s * (NEXP / NSPLIT);

    float ca0[4] = {}, ca1[4] = {}, cb0[4] = {}, cb1[4] = {};

    for (int r = warp; r < NEXP / NSPLIT; r += 8) {
        int n = n0 + r;
        const uint32_t* zr = reinterpret_cast<const uint32_t*>(ZM + ((size_t)b * NEXP + n) * LEN);
        float sa = 0.f, sb = 0.f;
        #pragma unroll
        for (int c = 0; c < 4; c++) {
            uint32_t u = zr[c * 32 + lane];
            float lo = bflo(u), hi = bfhi(u);
            float fa0 = fmaxf(lo, 0.f), fa1 = fmaxf(hi, 0.f);
            float fb0 = fmaxf(-lo, 0.f), fb1 = fmaxf(-hi, 0.f);
            sa += fa0 + fa1; sb += fb0 + fb1;
            ca0[c] += fa0; ca1[c] += fa1;
            cb0[c] += fb0; cb1[c] += fb1;
        }
        #pragma unroll
        for (int o = 16; o; o >>= 1) {
            sa += __shfl_down_sync(0xffffffffu, sa, o);
            sb += __shfl_down_sync(0xffffffffu, sb, o);
        }
        if (!lane) {
            invA[b * NEXP + n] = 1.f / (sa + 1e-9f);
            invB[b * NEXP + n] = 1.f / (sb + 1e-9f);
        }
    }
    #pragma unroll
    for (int c = 0; c < 4; c++) {
        colA[warp][c * 64 + 2 * lane]     = ca0[c];
        colA[warp][c * 64 + 2 * lane + 1] = ca1[c];
        colB[warp][c * 64 + 2 * lane]     = cb0[c];
        colB[warp][c * 64 + 2 * lane + 1] = cb1[c];
    }
    __syncthreads();
    int l = threadIdx.x;
    float sa = 0.f, sb = 0.f;
    #pragma unroll
    for (int w = 0; w < 8; w++) { sa += colA[w][l]; sb += colB[w][l]; }
    psA[((size_t)b * NSPLIT + s) * LEN + l] = sa;
    psB[((size_t)b * NSPLIT + s) * LEN + l] = sb;
}

// ------------------------- forward class GEMM + folded bw_final ------------------------------
__global__ void __launch_bounds__(256) classfw_bf16(
    const bf16* __restrict__ ZM,
    const bf16* __restrict__ AE, const bf16* __restrict__ BE,
    const float* __restrict__ invA, const float* __restrict__ invB,
    const int* __restrict__ nidx, const float* __restrict__ btab,
    bf16* __restrict__ CA, bf16* __restrict__ CB,
    const float* __restrict__ psA, const float* __restrict__ psB,
    float* __restrict__ invAb, float* __restrict__ invBb)
{
    __shared__ uint32_t sm[2][CF_STAGE];
    int bid = blockIdx.x;
    int tid = threadIdx.x;
    if (bid >= 4096) {
        // folded bw_final: 64 blocks, 256 threads each handle one (b, all l)
        int b = bid - 4096;
        int l = tid;
        float sa = 0.f, sb = 0.f;
        #pragma unroll
        for (int s = 0; s < NSPLIT; s++) {
            sa += psA[((size_t)b * NSPLIT + s) * LEN + l];
            sb += psB[((size_t)b * NSPLIT + s) * LEN + l];
        }
        invAb[b * LEN + l] = 1.f / (sa + 1e-9f);
        invBb[b * LEN + l] = 1.f / (sb + 1e-9f);
        return;
    }
    // GEMM part: decompose flattened bid -> (b, bm-tile, bn-tile); 8 n-tiles x 8 d-tiles per batch
    int b  = bid >> 6;
    int bm = ((bid >> 3) & 7) * 128;
    int bn = (bid & 7) * 64;
    int warp = tid >> 5, lane = tid & 31;
    int wr = warp >> 1, wc = warp & 1;
    int g = lane >> 2, t4 = lane & 3;

    float acca[2][4][4] = {}, accb[2][4][4] = {};

    int anr = tid >> 1, alc8 = (tid & 1) * 8, alc2 = (tid & 1) * 4;
    int bl2 = tid >> 5, bdc = lane * 2;
    uint4 za; uint32_t rE0, rE1, rB0, rB1;

    auto loadregs = [&](int k0) {
        int n = bm + anr; if (n >= NEXP) n = NEXP - 1;
        za = *reinterpret_cast<const uint4*>(ZM + ((size_t)b * NEXP + n) * LEN + k0 + alc8);
        size_t e0 = ((size_t)b * LEN + k0 + 2 * bl2) * DM + bn + bdc;
        size_t e1 = e0 + DM;
        rE0 = *reinterpret_cast<const uint32_t*>(AE + e0);
        rE1 = *reinterpret_cast<const uint32_t*>(AE + e1);
        rB0 = *reinterpret_cast<const uint32_t*>(BE + e0);
        rB1 = *reinterpret_cast<const uint32_t*>(BE + e1);
    };
    auto storeregs = [&](int s) {
        uint32_t* Aa = &sm[s][0];
        uint32_t* Ab = &sm[s][CF_AB];
        uint32_t* Ba = &sm[s][2 * CF_AB];
        uint32_t* Bb = &sm[s][2 * CF_AB + CF_B];
        uint4 ua, ub;
        ua.x = bfrelu2(za.x); ub.x = bfrelu2(bfneg2(za.x));
        ua.y = bfrelu2(za.y); ub.y = bfrelu2(bfneg2(za.y));
        ua.z = bfrelu2(za.z); ub.z = bfrelu2(bfneg2(za.z));
        ua.w = bfrelu2(za.w); ub.w = bfrelu2(bfneg2(za.w));
        *reinterpret_cast<uint4*>(&Aa[anr * AFST + alc2]) = ua;
        *reinterpret_cast<uint4*>(&Ab[anr * AFST + alc2]) = ub;
        Ba[bl2 * BCST + bdc]     = __byte_perm(rE0, rE1, 0x5410);
        Ba[bl2 * BCST + bdc + 1] = __byte_perm(rE0, rE1, 0x7632);
        Bb[bl2 * BCST + bdc]     = __byte_perm(rB0, rB1, 0x5410);
        Bb[bl2 * BCST + bdc + 1] = __byte_perm(rB0, rB1, 0x7632);
    };
    auto compute = [&](int s) {
        const uint32_t* Aa = &sm[s][0];
        const uint32_t* Ab = &sm[s][CF_AB];
        const uint32_t* Ba = &sm[s][2 * CF_AB];
        const uint32_t* Bb = &sm[s][2 * CF_AB + CF_B];
        uint32_t afa[2][4], afb[2][4], bfa[4][2], bfb[4][2];
        #pragma unroll
        for (int c = 0; c < 2; c++) {
            int row = wr * 32 + c * 16 + g;
            afa[c][0] = Aa[row * AFST + t4];
            afa[c][1] = Aa[(row + 8) * AFST + t4];
            afa[c][2] = Aa[row * AFST + t4 + 4];
            afa[c][3] = Aa[(row + 8) * AFST + t4 + 4];
            afb[c][0] = Ab[row * AFST + t4];
            afb[c][1] = Ab[(row + 8) * AFST + t4];
            afb[c][2] = Ab[row * AFST + t4 + 4];
            afb[c][3] = Ab[(row + 8) * AFST + t4 + 4];
        }
        #pragma unroll
        for (int nb = 0; nb < 4; nb++) {
            int col = wc * 32 + nb * 8 + g;
            bfa[nb][0] = Ba[t4 * BCST + col];
            bfa[nb][1] = Ba[(t4 + 4) * BCST + col];
            bfb[nb][0] = Bb[t4 * BCST + col];
            bfb[nb][1] = Bb[(t4 + 4) * BCST + col];
        }
        #pragma unroll
        for (int c = 0; c < 2; c++)
            #pragma unroll
            for (int nb = 0; nb < 4; nb++) {
                mma16(acca[c][nb], afa[c], bfa[nb]);
                mma16(accb[c][nb], afb[c], bfb[nb]);
            }
    };

    loadregs(0);
    storeregs(0);
    __syncthreads();
    const int KT = LEN / 16;
    for (int t = 0; t < KT; t++) {
        if (t + 1 < KT) loadregs((t + 1) * 16);
        compute(t & 1);
        if (t + 1 < KT) storeregs((t + 1) & 1);
        __syncthreads();
    }

    #pragma unroll
    for (int c = 0; c < 2; c++) {
        #pragma unroll
        for (int h = 0; h < 2; h++) {
            int n = bm + wr * 32 + c * 16 + g + h * 8;
            if (n >= NEXP) continue;
            float ia = invA[b * NEXP + n];
            float ib = invB[b * NEXP + n];
            int qi = nidx[b * NEXP + n];
            #pragma unroll
            for (int nb = 0; nb < 4; nb++) {
                int d0 = bn + wc * 32 + nb * 8 + 2 * t4;
                float2 bi = *reinterpret_cast<const float2*>(btab + (size_t)qi * DM + d0);
                size_t off = ((size_t)b * NEXP + n) * DM + d0;
                *reinterpret_cast<uint32_t*>(CA + off) =
                    f2bf2(acca[c][nb][h * 2 + 0] * ia + bi.x,
                          acca[c][nb][h * 2 + 1] * ia + bi.y);
                *reinterpret_cast<uint32_t*>(CB + off) =
                    f2bf2(accb[c][nb][h * 2 + 0] * ib + bi.x,
                          accb[c][nb][h * 2 + 1] * ib + bi.y);
            }
        }
    }
}

// ------------------------- backward class GEMM (mma.sync dual) -------------------------------
__global__ void __launch_bounds__(256) classbw_bf16(
    const bf16* __restrict__ ZM,
    const bf16* __restrict__ CA, const bf16* __restrict__ CB,
    const float* __restrict__ invA, const float* __restrict__ invB,
    const float* __restrict__ SELp, const float* __restrict__ X,
    float* __restrict__ X1)
{
    __shared__ uint32_t sm[2][CB_STAGE];
    int tid = threadIdx.x;
    int b  = blockIdx.z;
    int bl = blockIdx.y * 128;
    int bn = blockIdx.x * 64;
    int warp = tid >> 5, lane = tid & 31;
    int wr = warp >> 1, wc = warp & 1;
    int g = lane >> 2, t4 = lane & 3;

    float acca[2][4][4] = {}, accb[2][4][4] = {};

    int n2 = tid >> 5, l4 = lane * 4;
    int bdc = lane * 2;
    uint2 ze, zo; uint32_t rC0, rC1, rD0, rD1;

    auto loadregs = [&](int k0) {
        size_t z0 = ((size_t)b * NEXP + k0 + 2 * n2) * LEN + bl + l4;
        ze = *reinterpret_cast<const uint2*>(ZM + z0);
        zo = *reinterpret_cast<const uint2*>(ZM + z0 + LEN);
        size_t c0 = ((size_t)b * NEXP + k0 + 2 * n2) * DM + bn + bdc;
        size_t c1 = c0 + DM;
        rC0 = *reinterpret_cast<const uint32_t*>(CA + c0);
        rC1 = *reinterpret_cast<const uint32_t*>(CA + c1);
        rD0 = *reinterpret_cast<const uint32_t*>(CB + c0);
        rD1 = *reinterpret_cast<const uint32_t*>(CB + c1);
    };
    auto storeregs = [&](int s) {
        uint32_t* Aa = &sm[s][0];
        uint32_t* Ab = &sm[s][CB_AB];
        uint32_t* Ba = &sm[s][2 * CB_AB];
        uint32_t* Bb = &sm[s][2 * CB_AB + CF_B];
        uint32_t p[4];
        p[0] = __byte_perm(ze.x, zo.x, 0x5410);
        p[1] = __byte_perm(ze.x, zo.x, 0x7632);
        p[2] = __byte_perm(ze.y, zo.y, 0x5410);
        p[3] = __byte_perm(ze.y, zo.y, 0x7632);
        #pragma unroll
        for (int i = 0; i < 4; i++) {
            Aa[(l4 + i) * ABST + n2] = bfrelu2(p[i]);
            Ab[(l4 + i) * ABST + n2] = bfrelu2(bfneg2(p[i]));
        }
        Ba[n2 * BCST + bdc]     = __byte_perm(rC0, rC1, 0x5410);
        Ba[n2 * BCST + bdc + 1] = __byte_perm(rC0, rC1, 0x7632);
        Bb[n2 * BCST + bdc]     = __byte_perm(rD0, rD1, 0x5410);
        Bb[n2 * BCST + bdc + 1] = __byte_perm(rD0, rD1, 0x7632);
    };
    auto compute = [&](int s) {
        const uint32_t* Aa = &sm[s][0];
        const uint32_t* Ab = &sm[s][CB_AB];
        const uint32_t* Ba = &sm[s][2 * CB_AB];
        const uint32_t* Bb = &sm[s][2 * CB_AB + CF_B];
        uint32_t afa[2][4], afb[2][4], bfa[4][2], bfb[4][2];
        #pragma unroll
        for (int c = 0; c < 2; c++) {
            int row = wr * 32 + c * 16 + g;
            afa[c][0] = Aa[row * ABST + t4];
            afa[c][1] = Aa[(row + 8) * ABST + t4];
            afa[c][2] = Aa[row * ABST + t4 + 4];
            afa[c][3] = Aa[(row + 8) * ABST + t4 + 4];
            afb[c][0] = Ab[row * ABST + t4];
            afb[c][1] = Ab[(row + 8) * ABST + t4];
            afb[c][2] = Ab[row * ABST + t4 + 4];
            afb[c][3] = Ab[(row + 8) * ABST + t4 + 4];
        }
        #pragma unroll
        for (int nb = 0; nb < 4; nb++) {
            int col = wc * 32 + nb * 8 + g;
            bfa[nb][0] = Ba[t4 * BCST + col];
            bfa[nb][1] = Ba[(t4 + 4) * BCST + col];
            bfb[nb][0] = Bb[t4 * BCST + col];
            bfb[nb][1] = Bb[(t4 + 4) * BCST + col];
        }
        #pragma unroll
        for (int c = 0; c < 2; c++)
            #pragma unroll
            for (int nb = 0; nb < 4; nb++) {
                mma16(acca[c][nb], afa[c], bfa[nb]);
                mma16(accb[c][nb], afb[c], bfb[nb]);
            }
    };

    loadregs(0);
    storeregs(0);
    __syncthreads();
    const int KT = NEXP / 16;
    for (int t = 0; t < KT; t++) {
        if (t + 1 < KT) loadregs((t + 1) * 16);
        compute(t & 1);
        if (t + 1 < KT) storeregs((t + 1) & 1);
        __syncthreads();
    }

    #pragma unroll
    for (int c = 0; c < 2; c++) {
        #pragma unroll
        for (int h = 0; h < 2; h++) {
            int l = bl + wr * 32 + c * 16 + g + h * 8;
            float ia = invA[b * LEN + l];
            float ib = invB[b * LEN + l];
            #pragma unroll
            for (int nb = 0; nb < 4; nb++) {
                int d0 = bn + wc * 32 + nb * 8 + 2 * t4;
                size_t off = ((size_t)b * LEN + l) * DM + d0;
                float2 s2 = *reinterpret_cast<const float2*>(SELp + off);
                float2 x2 = *reinterpret_cast<const float2*>(X + off);
                float2 o;
                o.x = x2.x + s2.x * (acca[c][nb][h * 2 + 0] * ia)
                           + (1.f - s2.x) * (accb[c][nb][h * 2 + 0] * ib);
                o.y = x2.y + s2.y * (acca[c][nb][h * 2 + 1] * ia)
                           + (1.f - s2.y) * (accb[c][nb][h * 2 + 1] * ib);
                *reinterpret_cast<float2*>(X1 + off) = o;
            }
        }
    }
}

// ------------------------- launch -------------------------
extern "C" void kernel_launch(void* const* d_in, const int* in_sizes, int n_in,
                              void* d_out, int out_size)
{
    const float* x     = (const float*)d_in[0];
    const int*   nidx  = (const int*)d_in[1];
    const int*   mask  = (const int*)d_in[2];
    const float* ln1_g = (const float*)d_in[3];
    const float* ln1_b = (const float*)d_in[4];
    const float* ln2_g = (const float*)d_in[5];
    const float* ln2_b = (const float*)d_in[6];
    const float* q_tab = (const float*)d_in[7];
    const float* b_tab = (const float*)d_in[8];
    const float* Wk  = (const float*)d_in[9];  const float* bk   = (const float*)d_in[10];
    const float* Wa  = (const float*)d_in[11]; const float* ba   = (const float*)d_in[12];
    const float* Wa1 = (const float*)d_in[13]; const float* ba1  = (const float*)d_in[14];
    const float* Wb  = (const float*)d_in[15]; const float* bb   = (const float*)d_in[16];
    const float* Wb1 = (const float*)d_in[17]; const float* bb1  = (const float*)d_in[18];
    const float* Ws  = (const float*)d_in[19]; const float* bsel = (const float*)d_in[20];
    const float* Wf1 = (const float*)d_in[21]; const float* bf1  = (const float*)d_in[22];
    const float* Wf2 = (const float*)d_in[23]; const float* bf2  = (const float*)d_in[24];
    float* out = (float*)d_out;

    bf16 *pX2, *pXK, *pEA0, *pEB0, *pAE, *pBE, *pZM, *pCA, *pCB, *pH, *pWH, *pQH;
    float *pSEL, *pX1, *pIAf, *pIBf, *pPA, *pPB, *pIAb, *pIBb;
    cudaGetSymbolAddress((void**)&pX2, g_X2);
    cudaGetSymbolAddress((void**)&pXK, g_XK);
    cudaGetSymbolAddress((void**)&pEA0, g_EA0);
    cudaGetSymbolAddress((void**)&pEB0, g_EB0);
    cudaGetSymbolAddress((void**)&pAE, g_AE);
    cudaGetSymbolAddress((void**)&pBE, g_BE);
    cudaGetSymbolAddress((void**)&pSEL, g_SEL);
    cudaGetSymbolAddress((void**)&pX1, g_X1);
    cudaGetSymbolAddress((void**)&pZM, g_ZM);
    cudaGetSymbolAddress((void**)&pCA, g_CA);
    cudaGetSymbolAddress((void**)&pCB, g_CB);
    cudaGetSymbolAddress((void**)&pH, g_H);
    cudaGetSymbolAddress((void**)&pIAf, g_IAf);
    cudaGetSymbolAddress((void**)&pIBf, g_IBf);
    cudaGetSymbolAddress((void**)&pPA, g_PA);
    cudaGetSymbolAddress((void**)&pPB, g_PB);
    cudaGetSymbolAddress((void**)&pIAb, g_IAb);
    cudaGetSymbolAddress((void**)&pIBb, g_IBb);
    cudaGetSymbolAddress((void**)&pWH, g_WH);
    cudaGetSymbolAddress((void**)&pQH, g_QH);

    bf16* WkH  = pWH;
    bf16* WaH  = pWH + 262144;
    bf16* WbH  = pWH + 524288;
    bf16* WsH  = pWH + 786432;
    bf16* Wa1H = pWH + 1048576;
    bf16* Wb1H = pWH + 1310720;
    bf16* Wf1H = pWH + 1572864;
    bf16* Wf2H = pWH + 2621440;

    // 0. fused LN1 + weight conversion (1 launch, 128-thread blocks)
    CvtArgs ca;
    ca.s[0] = Wk;  ca.d[0] = WkH;
    ca.s[1] = Wa;  ca.d[1] = WaH;
    ca.s[2] = Wb;  ca.d[2] = WbH;
    ca.s[3] = Ws;  ca.d[3] = WsH;
    ca.s[4] = Wa1; ca.d[4] = Wa1H;
    ca.s[5] = Wb1; ca.d[5] = Wb1H;
    ca.s[6] = Wf1; ca.d[6] = Wf1H;
    ca.s[7] = Wf2; ca.d[7] = Wf2H;
    ca.s[8] = q_tab; ca.d[8] = pQH;
    int sizes4[9] = {65536, 65536, 65536, 65536, 65536, 65536, 262144, 262144, 126976};
    ca.cum[0] = 0;
    for (int i = 0; i < 9; i++) ca.cum[i + 1] = ca.cum[i] + sizes4[i];
    int cvtBlocks = (ca.cum[9] + 127) / 128;
    prep_fused<<<M1 + cvtBlocks, 128>>>(x, ln1_g, ln1_b, pX2, ca);

    // 1. merged dense projections {Wk, Wa, Wb, Ws}
    GArg gk = {pX2, WkH, bk,   nullptr, pXK,  0};
    GArg ga_ = {pX2, WaH, ba,  nullptr, pEA0, 0};
    GArg gb = {pX2, WbH, bb,   nullptr, pEB0, 0};
    GArg gs = {pX2, WsH, bsel, nullptr, pSEL, 1};
    gemm_multi<<<dim3(DM / 128, M1 / 128, 4), 256>>>(gk, ga_, gb, gs, M1, DM, DM);

    // 2. fused step3+4: gated projections {Wa1, Wb1} interleaved with z GEMM
    GArg g1 = {pEA0, Wa1H, ba1, pEA0, pAE, 3};
    GArg g2 = {pEB0, Wb1H, bb1, pEB0, pBE, 3};
    step34_fused<<<2048, 256>>>(g1, g2, nidx, pQH, pXK, mask, pZM);

    // 3. sums (fw row sums + bw column partials)
    sums_fused<<<dim3(BSZ, NSPLIT), 256>>>(pZM, pIAf, pIBf, pPA, pPB);

    // 4. classfw + folded bw_final (bw_final consumes psA/psB; its output feeds classbw only)
    classfw_bf16<<<4096 + 64, 256>>>(pZM, pAE, pBE, pIAf, pIBf, nidx, b_tab,
                                     pCA, pCB, pPA, pPB, pIAb, pIBb);

    // 5. classbw
    classbw_bf16<<<dim3(DM / 64, LEN / 128, BSZ), 256>>>(
        pZM, pCA, pCB, pIAb, pIBb, pSEL, x, pX1);

    // 6. LN2 + FFN
    ln_kernel<<<M1, 128>>>(pX1, ln2_g, ln2_b, pX2);
    GArg gf1 = {pX2, Wf1H, bf1, nullptr, pH, 2};
    gemm_multi<<<dim3(DFF / 128, M1 / 128, 1), 256>>>(gf1, gf1, gf1, gf1, M1, DFF, DM);
    GArg gf2 = {pH, Wf2H, bf2, pX1, out, 4};
    gemm_multi<<<dim3(DM / 128, M1 / 128, 1), 256>>>(gf2, gf2, gf2, gf2, M1, DM, DFF);
}